// round 12
// baseline (speedup 1.0000x reference)
#include <cuda_runtime.h>
#include <cstdint>

// Problem constants
#define BB 4
#define TT 2048
#define EE 1024
#define HH 16
#define HD 64
#define BT (BB * TT)   // 8192 rows

// ---------------------------------------------------------------------------
// Scratch (static __device__ arrays; no runtime allocation allowed)
// ---------------------------------------------------------------------------
__device__ float g_Q[BB * HH * TT * HD];   // [b,h,t,d], q pre-scaled
__device__ float g_K[BB * HH * TT * HD];
__device__ float g_V[BB * HH * TT * HD];
__device__ float g_AO[BT * EE];            // attention output, [b,t,e]

// ---------------------------------------------------------------------------
// tf32 / cp.async helpers (all sm_80+ PTX — valid at plain sm_100 target)
// ---------------------------------------------------------------------------
__device__ __forceinline__ uint32_t f2tf32(float f) {
    uint32_t r;
    asm("cvt.rna.tf32.f32 %0, %1;" : "=r"(r) : "f"(f));
    return r;
}

__device__ __forceinline__ void mma_tf32_16x8x8(
    float& c0, float& c1, float& c2, float& c3,
    uint32_t a0, uint32_t a1, uint32_t a2, uint32_t a3,
    uint32_t b0, uint32_t b1) {
    asm volatile(
        "mma.sync.aligned.m16n8k8.row.col.f32.tf32.tf32.f32 "
        "{%0,%1,%2,%3}, {%4,%5,%6,%7}, {%8,%9}, {%0,%1,%2,%3};"
        : "+f"(c0), "+f"(c1), "+f"(c2), "+f"(c3)
        : "r"(a0), "r"(a1), "r"(a2), "r"(a3), "r"(b0), "r"(b1));
}

__device__ __forceinline__ void cp_async16(uint32_t dst_smem, const void* src) {
    asm volatile("cp.async.cg.shared.global [%0], [%1], 16;"
                 :: "r"(dst_smem), "l"(src));
}
#define CP_COMMIT() asm volatile("cp.async.commit_group;" ::: "memory")
#define CP_WAIT(N)  asm volatile("cp.async.wait_group %0;" :: "n"(N) : "memory")

// ---------------------------------------------------------------------------
// Kernel 1: tf32 mma.sync per-head QKV projection (unchanged — known correct)
// ---------------------------------------------------------------------------
#define QK_LD   68
#define QK_SMEM ((128 * QK_LD + 192 * QK_LD) * 4)   // 87040 B (dynamic)

__global__ __launch_bounds__(256, 1)
void qkv_mma_kernel(const float* __restrict__ x,
                    const float* __restrict__ Wq,
                    const float* __restrict__ bq) {
    extern __shared__ uint32_t qsm[];
    uint32_t* Xs = qsm;                   // [128][68], [r][k]
    uint32_t* Ws = qsm + 128 * QK_LD;     // [192][68], [n][k]  (transposed W)

    const int h    = blockIdx.y;
    const int row0 = blockIdx.x * 128;    // over B*T
    const int tid  = threadIdx.x;
    const int wid  = tid >> 5;
    const int lane = tid & 31;
    const int lrow = lane >> 2;           // 0..7
    const int lcol = lane & 3;            // 0..3

    const int warp_m = (wid & 1) * 64;    // 0 or 64
    const int warp_n = (wid >> 1) * 48;   // 0,48,96,144

#pragma unroll
    for (int it = 0; it < 8; it++) {
        const int i = it * 256 + tid;     // 0..2047 float4s
        const int r = i >> 4, c = (i & 15) * 4;
        const float4 v = *(const float4*)&x[(size_t)(row0 + r) * EE + h * HD + c];
        *(uint4*)&Xs[r * QK_LD + c] =
            make_uint4(f2tf32(v.x), f2tf32(v.y), f2tf32(v.z), f2tf32(v.w));
    }

    const float* Wh = Wq + (size_t)h * 64 * 192;
#pragma unroll
    for (int it = 0; it < 12; it++) {
        const int i = it * 256 + tid;     // 0..3071 float4s
        const int d = i / 48, c = (i % 48) * 4;
        const float4 v = *(const float4*)&Wh[d * 192 + c];
        Ws[(c + 0) * QK_LD + d] = f2tf32(v.x);
        Ws[(c + 1) * QK_LD + d] = f2tf32(v.y);
        Ws[(c + 2) * QK_LD + d] = f2tf32(v.z);
        Ws[(c + 3) * QK_LD + d] = f2tf32(v.w);
    }
    __syncthreads();

    float c[4][6][4];
#pragma unroll
    for (int m = 0; m < 4; m++)
#pragma unroll
        for (int n = 0; n < 6; n++)
#pragma unroll
            for (int f = 0; f < 4; f++) c[m][n][f] = 0.f;

#pragma unroll
    for (int ks = 0; ks < 8; ks++) {
        const int kk = ks * 8;
        uint32_t a[4][4], b[6][2];
#pragma unroll
        for (int m = 0; m < 4; m++) {
            const int ar = warp_m + m * 16 + lrow;
            a[m][0] = Xs[ar * QK_LD + kk + lcol];
            a[m][1] = Xs[(ar + 8) * QK_LD + kk + lcol];
            a[m][2] = Xs[ar * QK_LD + kk + 4 + lcol];
            a[m][3] = Xs[(ar + 8) * QK_LD + kk + 4 + lcol];
        }
#pragma unroll
        for (int n = 0; n < 6; n++) {
            const int br = warp_n + n * 8 + lrow;
            b[n][0] = Ws[br * QK_LD + kk + lcol];
            b[n][1] = Ws[br * QK_LD + kk + 4 + lcol];
        }
#pragma unroll
        for (int m = 0; m < 4; m++)
#pragma unroll
            for (int n = 0; n < 6; n++)
                mma_tf32_16x8x8(c[m][n][0], c[m][n][1], c[m][n][2], c[m][n][3],
                                a[m][0], a[m][1], a[m][2], a[m][3],
                                b[n][0], b[n][1]);
    }

    const float scale = (float)(1.0 / (8.0 + 1e-5));
#pragma unroll
    for (int n = 0; n < 6; n++) {
        const int col = warp_n + n * 8 + 2 * lcol;   // 0..191
        const int sec = col >> 6;                    // 0=q,1=k,2=v
        const int d   = col & 63;
        const float b0 = bq[h * 192 + col];
        const float b1 = bq[h * 192 + col + 1];
        float* dst = (sec == 0) ? g_Q : (sec == 1) ? g_K : g_V;
        const float mul = (sec == 0) ? scale : 1.0f;
#pragma unroll
        for (int m = 0; m < 4; m++) {
            const int r  = row0 + warp_m + m * 16 + lrow;
            const int b_ = r / TT;
            const int t  = r - b_ * TT;
            const size_t off = ((size_t)(b_ * HH + h) * TT + t) * HD + d;
            *(float2*)&dst[off] =
                make_float2((c[m][n][0] + b0) * mul, (c[m][n][1] + b1) * mul);
            const size_t off2 = off + (size_t)8 * HD;   // row r+8, same b_ (128 | TT)
            *(float2*)&dst[off2] =
                make_float2((c[m][n][2] + b0) * mul, (c[m][n][3] + b1) * mul);
        }
    }
}

// ---------------------------------------------------------------------------
// Kernel 2 (R12): tf32 mma.sync causal flash attention.
//   R7 shape (BM=64, 128 thr, occ 4) + in-place cp.async staging (no extra
//   smem, no extra regs), global big-first grid order, diagonal mma skip.
// ---------------------------------------------------------------------------
#define AT_LDQ 68   // Qs / P stride (uint32 elems)
#define AT_LDK 68   // Ks stride
#define AT_LDV 72   // Vs stride
#define AT_SMEM ((64 * AT_LDQ + 64 * AT_LDK + 64 * AT_LDV) * 4)   // 53248 B

__global__ __launch_bounds__(128, 4)
void attn_mma_kernel() {
    extern __shared__ uint32_t asm_[];
    uint32_t* Qs = asm_;                          // 64 x 68 (Q tile, later P)
    uint32_t* Ks = Qs + 64 * AT_LDQ;              // 64 x 68 raw fp32, [c][d]
    uint32_t* Vs = Ks + 64 * AT_LDK;              // 64 x 72 raw fp32, [c][d]

    const int bh = blockIdx.x;                    // bh on x
    const int qt = gridDim.y - 1 - blockIdx.y;    // ALL big tiles first chip-wide
    const int q0 = qt * 64;
    const float* Qp = g_Q + (size_t)bh * TT * HD;
    const float* Kp = g_K + (size_t)bh * TT * HD;
    const float* Vp = g_V + (size_t)bh * TT * HD;

    const int tid  = threadIdx.x;
    const int wid  = tid >> 5;
    const int lane = tid & 31;
    const int lrow = lane >> 2;    // 0..7
    const int lcol = lane & 3;     // 0..3
    const int wm   = wid * 16;     // warp's row base within tile

    const uint32_t smem_u32 = (uint32_t)__cvta_generic_to_shared(asm_);
    const uint32_t koff = smem_u32 + 64 * AT_LDQ * 4;
    const uint32_t voff = koff + 64 * AT_LDK * 4;

    // stage K or V tile kt via cp.async (raw fp32), one commit group each
    auto stage_k = [&](int kt) {
        const int kbase = kt * 64;
#pragma unroll
        for (int it = 0; it < 8; it++) {
            const int i = it * 128 + tid;          // 0..1023 float4s
            const int r = i >> 4, d = (i & 15) * 4;
            cp_async16(koff + (uint32_t)(r * AT_LDK + d) * 4,
                       Kp + (size_t)(kbase + r) * HD + d);
        }
        CP_COMMIT();
    };
    auto stage_v = [&](int kt) {
        const int kbase = kt * 64;
#pragma unroll
        for (int it = 0; it < 8; it++) {
            const int i = it * 128 + tid;
            const int r = i >> 4, d = (i & 15) * 4;
            cp_async16(voff + (uint32_t)(r * AT_LDV + d) * 4,
                       Vp + (size_t)(kbase + r) * HD + d);
        }
        CP_COMMIT();
    };

    // ---- start K0/V0 loads first, then stage Q while they fly ----
    stage_k(0);
    stage_v(0);

#pragma unroll
    for (int it = 0; it < 8; it++) {
        const int i = it * 512 + tid * 4;         // 0..4095
        const int r = i >> 6, d = i & 63;
        const float4 v = *(const float4*)&Qp[(size_t)(q0 + r) * HD + d];
        *(uint4*)&Qs[r * AT_LDQ + d] =
            make_uint4(f2tf32(v.x), f2tf32(v.y), f2tf32(v.z), f2tf32(v.w));
    }
    __syncthreads();

    uint32_t qf[8][4];
#pragma unroll
    for (int ks = 0; ks < 8; ks++) {
        const int base = (wm + lrow) * AT_LDQ + ks * 8 + lcol;
        qf[ks][0] = Qs[base];
        qf[ks][1] = Qs[base + 8 * AT_LDQ];
        qf[ks][2] = Qs[base + 4];
        qf[ks][3] = Qs[base + 8 * AT_LDQ + 4];
    }
    __syncthreads();   // Qs becomes the P buffer from here on

    float o[8][4];
#pragma unroll
    for (int n = 0; n < 8; n++)
#pragma unroll
        for (int f = 0; f < 4; f++) o[n][f] = 0.f;
    float m0 = -1e30f, m1 = -1e30f, l0 = 0.f, l1 = 0.f;

    const int r0g = q0 + wm + lrow;     // global row of frag-half 0
    const int r1g = r0g + 8;

    for (int kt = 0; kt <= qt; kt++) {
        const int kbase = kt * 64;
        // wait K(kt): it is the older of the (at most 2) pending groups
        CP_WAIT(1);
        __syncthreads();               // K(kt) visible to all warps

        // limit for diagonal tile: n/ks groups with col-min > warp row-max are
        // fully masked -> skip mma (bit-identical: P entries there are exact 0)
        const int hi = (kt == qt) ? ((wm + 15) >> 3) : 7;

        // ---- S = Q K^T (K raw fp32 -> cvt at fragment load) ----
        float s[8][4];
#pragma unroll
        for (int n = 0; n < 8; n++)
#pragma unroll
            for (int f = 0; f < 4; f++) s[n][f] = 0.f;

#pragma unroll
        for (int ks = 0; ks < 8; ks++) {
            const int kk = ks * 8;
#pragma unroll
            for (int n = 0; n < 8; n++) {
                if (n <= hi) {
                    const int kr = (n * 8 + lrow) * AT_LDK + kk + lcol;
                    const uint32_t b0 = f2tf32(__uint_as_float(Ks[kr]));
                    const uint32_t b1 = f2tf32(__uint_as_float(Ks[kr + 4]));
                    mma_tf32_16x8x8(s[n][0], s[n][1], s[n][2], s[n][3],
                                    qf[ks][0], qf[ks][1], qf[ks][2], qf[ks][3],
                                    b0, b1);
                }
            }
        }
        __syncthreads();               // all warps done reading Ks
        if (kt < qt) stage_k(kt + 1);  // overwrite Ks while we do softmax+PV

        if (kt == qt) {   // causal mask on diagonal tile (covers skipped tiles)
#pragma unroll
            for (int n = 0; n < 8; n++) {
                const int cg = kbase + n * 8 + 2 * lcol;
                if (cg     > r0g) s[n][0] = -1e30f;
                if (cg + 1 > r0g) s[n][1] = -1e30f;
                if (cg     > r1g) s[n][2] = -1e30f;
                if (cg + 1 > r1g) s[n][3] = -1e30f;
            }
        }

        // ---- online softmax (registers + quad shuffle) ----
        float mx0 = m0, mx1 = m1;
#pragma unroll
        for (int n = 0; n < 8; n++) {
            mx0 = fmaxf(mx0, fmaxf(s[n][0], s[n][1]));
            mx1 = fmaxf(mx1, fmaxf(s[n][2], s[n][3]));
        }
        mx0 = fmaxf(mx0, __shfl_xor_sync(0xffffffffu, mx0, 1));
        mx0 = fmaxf(mx0, __shfl_xor_sync(0xffffffffu, mx0, 2));
        mx1 = fmaxf(mx1, __shfl_xor_sync(0xffffffffu, mx1, 1));
        mx1 = fmaxf(mx1, __shfl_xor_sync(0xffffffffu, mx1, 2));

        float sum0 = 0.f, sum1 = 0.f;
#pragma unroll
        for (int n = 0; n < 8; n++) {
            s[n][0] = __expf(s[n][0] - mx0);
            s[n][1] = __expf(s[n][1] - mx0);
            s[n][2] = __expf(s[n][2] - mx1);
            s[n][3] = __expf(s[n][3] - mx1);
            sum0 += s[n][0] + s[n][1];
            sum1 += s[n][2] + s[n][3];
        }
        sum0 += __shfl_xor_sync(0xffffffffu, sum0, 1);
        sum0 += __shfl_xor_sync(0xffffffffu, sum0, 2);
        sum1 += __shfl_xor_sync(0xffffffffu, sum1, 1);
        sum1 += __shfl_xor_sync(0xffffffffu, sum1, 2);

        const float cf0 = __expf(m0 - mx0);
        const float cf1 = __expf(m1 - mx1);
        l0 = l0 * cf0 + sum0;  m0 = mx0;
        l1 = l1 * cf1 + sum1;  m1 = mx1;
#pragma unroll
        for (int n = 0; n < 8; n++) {
            o[n][0] *= cf0; o[n][1] *= cf0;
            o[n][2] *= cf1; o[n][3] *= cf1;
        }

        // wait V(kt): if K(kt+1) was just committed it is the newest pending
        if (kt < qt) { CP_WAIT(1); } else { CP_WAIT(0); }
        __syncthreads();               // V(kt) visible to all warps

        // ---- P -> smem (per-warp region of Qs), then PV (V cvt at load) ----
#pragma unroll
        for (int n = 0; n < 8; n++) {
            const int pr = (wm + lrow) * AT_LDQ + n * 8 + 2 * lcol;
            *(uint2*)&Qs[pr] = make_uint2(f2tf32(s[n][0]), f2tf32(s[n][1]));
            *(uint2*)&Qs[pr + 8 * AT_LDQ] = make_uint2(f2tf32(s[n][2]), f2tf32(s[n][3]));
        }
        __syncwarp();

#pragma unroll
        for (int ks = 0; ks < 8; ks++) {
            if (ks <= hi) {
                const int kk = ks * 8;
                const int pb = (wm + lrow) * AT_LDQ + kk + lcol;
                const uint32_t a0 = Qs[pb];
                const uint32_t a1 = Qs[pb + 8 * AT_LDQ];
                const uint32_t a2 = Qs[pb + 4];
                const uint32_t a3 = Qs[pb + 8 * AT_LDQ + 4];
#pragma unroll
                for (int n = 0; n < 8; n++) {
                    const uint32_t b0 = f2tf32(__uint_as_float(Vs[(kk + lcol) * AT_LDV + n * 8 + lrow]));
                    const uint32_t b1 = f2tf32(__uint_as_float(Vs[(kk + 4 + lcol) * AT_LDV + n * 8 + lrow]));
                    mma_tf32_16x8x8(o[n][0], o[n][1], o[n][2], o[n][3],
                                    a0, a1, a2, a3, b0, b1);
                }
            }
        }
        __syncthreads();               // all warps done reading Vs
        if (kt < qt) stage_v(kt + 1);  // overwrite Vs; lands during next QK
    }

    // ---- normalize and store ----
    const float inv0 = 1.0f / l0;
    const float inv1 = 1.0f / l1;
    const int b_ = bh >> 4, h = bh & 15;
    const size_t rowbase0 = (size_t)(b_ * TT + r0g) * EE + h * HD;
    const size_t rowbase1 = (size_t)(b_ * TT + r1g) * EE + h * HD;
#pragma unroll
    for (int n = 0; n < 8; n++) {
        const int d = n * 8 + 2 * lcol;
        *(float2*)&g_AO[rowbase0 + d] = make_float2(o[n][0] * inv0, o[n][1] * inv0);
        *(float2*)&g_AO[rowbase1 + d] = make_float2(o[n][2] * inv1, o[n][3] * inv1);
    }
}

// ---------------------------------------------------------------------------
// Kernel 3: tf32 mma.sync output projection, cp.async double-buffered
// (unchanged from R11 — known correct, 16 warps/SM register-bound)
// ---------------------------------------------------------------------------
#define PJ_LDA 36   // 32 + 4 pad (float4-aligned, conflict-free fragments)
#define PJ_SMEM (4 * 128 * PJ_LDA * 4)   // 73728 B

__global__ __launch_bounds__(256)
void proj_mma_kernel(const float* __restrict__ Wp,
                     const float* __restrict__ bp,
                     float* __restrict__ out) {
    extern __shared__ uint32_t psm[];
    uint32_t* Ab[2] = { psm,                  psm + 2 * 128 * PJ_LDA };
    uint32_t* Bb[2] = { psm + 128 * PJ_LDA,   psm + 3 * 128 * PJ_LDA };

    const int tid  = threadIdx.x;
    const int wid  = tid >> 5;
    const int lane = tid & 31;
    const int row0 = blockIdx.x * 128;
    const int col0 = blockIdx.y * 128;

    const uint32_t smem_u32 = (uint32_t)__cvta_generic_to_shared(psm);
    const uint32_t aoff[2] = { smem_u32,                         smem_u32 + 2 * 128 * PJ_LDA * 4 };
    const uint32_t boff[2] = { smem_u32 + 128 * PJ_LDA * 4,      smem_u32 + 3 * 128 * PJ_LDA * 4 };

    const int warp_m = (wid & 1) * 64;   // 0 or 64
    const int warp_n = (wid >> 1) * 32;  // 0,32,64,96

    auto stage = [&](int kt, int buf) {
        const int k0 = kt * 32;
#pragma unroll
        for (int it = 0; it < 4; it++) {
            const int lin = it * 1024 + tid * 4;   // 0..4095
            const int r = lin >> 5, cc = lin & 31;
            cp_async16(aoff[buf] + (uint32_t)(r * PJ_LDA + cc) * 4,
                       &g_AO[(size_t)(row0 + r) * EE + k0 + cc]);
            cp_async16(boff[buf] + (uint32_t)(r * PJ_LDA + cc) * 4,
                       &Wp[(size_t)(col0 + r) * EE + k0 + cc]);
        }
        CP_COMMIT();
    };

    float c[4][4][4];   // [m16][n8][frag]
#pragma unroll
    for (int m = 0; m < 4; m++)
#pragma unroll
        for (int n = 0; n < 4; n++)
#pragma unroll
            for (int f = 0; f < 4; f++) c[m][n][f] = 0.f;

    const int lrow = lane >> 2;    // 0..7
    const int lcol = lane & 3;     // 0..3

    stage(0, 0);
    stage(1, 1);

    for (int kt = 0; kt < EE / 32; kt++) {
        if (kt < EE / 32 - 1) { CP_WAIT(1); } else { CP_WAIT(0); }
        __syncthreads();
        const int cur = kt & 1;
        const uint32_t* As = Ab[cur];
        const uint32_t* Bs = Bb[cur];

#pragma unroll
        for (int ks = 0; ks < 4; ks++) {
            const int kk = ks * 8;
            uint32_t a[4][4], b[4][2];
#pragma unroll
            for (int m = 0; m < 4; m++) {
                const int ar = warp_m + m * 16 + lrow;
                a[m][0] = f2tf32(__uint_as_float(As[ar * PJ_LDA + kk + lcol]));
                a[m][1] = f2tf32(__uint_as_float(As[(ar + 8) * PJ_LDA + kk + lcol]));
                a[m][2] = f2tf32(__uint_as_float(As[ar * PJ_LDA + kk + 4 + lcol]));
                a[m][3] = f2tf32(__uint_as_float(As[(ar + 8) * PJ_LDA + kk + 4 + lcol]));
            }
#pragma unroll
            for (int n = 0; n < 4; n++) {
                const int br = warp_n + n * 8 + lrow;
                b[n][0] = f2tf32(__uint_as_float(Bs[br * PJ_LDA + kk + lcol]));
                b[n][1] = f2tf32(__uint_as_float(Bs[br * PJ_LDA + kk + 4 + lcol]));
            }
#pragma unroll
            for (int m = 0; m < 4; m++)
#pragma unroll
                for (int n = 0; n < 4; n++)
                    mma_tf32_16x8x8(c[m][n][0], c[m][n][1], c[m][n][2], c[m][n][3],
                                    a[m][0], a[m][1], a[m][2], a[m][3],
                                    b[n][0], b[n][1]);
        }

        __syncthreads();   // all warps done reading buf[cur] before refill
        if (kt + 2 < EE / 32) stage(kt + 2, cur);
    }

#pragma unroll
    for (int m = 0; m < 4; m++) {
#pragma unroll
        for (int n = 0; n < 4; n++) {
            const int col = col0 + warp_n + n * 8 + 2 * lcol;
            const int r1  = row0 + warp_m + m * 16 + lrow;
            const float b0 = bp[col], b1 = bp[col + 1];
            float2 o0 = make_float2(c[m][n][0] + b0, c[m][n][1] + b1);
            float2 o1 = make_float2(c[m][n][2] + b0, c[m][n][3] + b1);
            *(float2*)&out[(size_t)r1 * EE + col]       = o0;
            *(float2*)&out[(size_t)(r1 + 8) * EE + col] = o1;
        }
    }
}

// ---------------------------------------------------------------------------
// Launch
// ---------------------------------------------------------------------------
extern "C" void kernel_launch(void* const* d_in, const int* in_sizes, int n_in,
                              void* d_out, int out_size) {
    const float* x  = (const float*)d_in[0];
    const float* Wq = (const float*)d_in[1];
    const float* bq = (const float*)d_in[2];
    const float* Wp = (const float*)d_in[3];
    const float* bp = (const float*)d_in[4];
    float* out = (float*)d_out;

    cudaFuncSetAttribute(qkv_mma_kernel,  cudaFuncAttributeMaxDynamicSharedMemorySize, QK_SMEM);
    cudaFuncSetAttribute(attn_mma_kernel, cudaFuncAttributeMaxDynamicSharedMemorySize, AT_SMEM);
    cudaFuncSetAttribute(proj_mma_kernel, cudaFuncAttributeMaxDynamicSharedMemorySize, PJ_SMEM);

    qkv_mma_kernel<<<dim3(BT / 128, HH), 256, QK_SMEM>>>(x, Wq, bq);
    // bh on x, tile on y: all longest CTAs chip-wide launch first
    attn_mma_kernel<<<dim3(BB * HH, TT / 64), 128, AT_SMEM>>>();
    proj_mma_kernel<<<dim3(BT / 128, EE / 128), 256, PJ_SMEM>>>(Wp, bp, out);
}

// round 13
// speedup vs baseline: 1.0026x; 1.0026x over previous
#include <cuda_runtime.h>
#include <cstdint>

// Problem constants
#define BB 4
#define TT 2048
#define EE 1024
#define HH 16
#define HD 64
#define BT (BB * TT)   // 8192 rows

// ---------------------------------------------------------------------------
// Scratch (static __device__ arrays; no runtime allocation allowed)
// ---------------------------------------------------------------------------
__device__ float g_Q[BB * HH * TT * HD];   // [b,h,t,d], q pre-scaled
__device__ float g_K[BB * HH * TT * HD];
__device__ float g_V[BB * HH * TT * HD];
__device__ float g_AO[BT * EE];            // attention output, [b,t,e]

// ---------------------------------------------------------------------------
// tf32 / cp.async helpers (all sm_80+ PTX — valid at plain sm_100 target)
// ---------------------------------------------------------------------------
__device__ __forceinline__ uint32_t f2tf32(float f) {
    uint32_t r;
    asm("cvt.rna.tf32.f32 %0, %1;" : "=r"(r) : "f"(f));
    return r;
}

__device__ __forceinline__ void mma_tf32_16x8x8(
    float& c0, float& c1, float& c2, float& c3,
    uint32_t a0, uint32_t a1, uint32_t a2, uint32_t a3,
    uint32_t b0, uint32_t b1) {
    asm volatile(
        "mma.sync.aligned.m16n8k8.row.col.f32.tf32.tf32.f32 "
        "{%0,%1,%2,%3}, {%4,%5,%6,%7}, {%8,%9}, {%0,%1,%2,%3};"
        : "+f"(c0), "+f"(c1), "+f"(c2), "+f"(c3)
        : "r"(a0), "r"(a1), "r"(a2), "r"(a3), "r"(b0), "r"(b1));
}

__device__ __forceinline__ void cp_async16(uint32_t dst_smem, const void* src) {
    asm volatile("cp.async.cg.shared.global [%0], [%1], 16;"
                 :: "r"(dst_smem), "l"(src));
}
#define CP_COMMIT() asm volatile("cp.async.commit_group;" ::: "memory")
#define CP_WAIT(N)  asm volatile("cp.async.wait_group %0;" :: "n"(N) : "memory")

// ---------------------------------------------------------------------------
// Kernel 1: tf32 mma.sync per-head QKV projection (unchanged — known correct)
// ---------------------------------------------------------------------------
#define QK_LD   68
#define QK_SMEM ((128 * QK_LD + 192 * QK_LD) * 4)   // 87040 B (dynamic)

__global__ __launch_bounds__(256, 1)
void qkv_mma_kernel(const float* __restrict__ x,
                    const float* __restrict__ Wq,
                    const float* __restrict__ bq) {
    extern __shared__ uint32_t qsm[];
    uint32_t* Xs = qsm;                   // [128][68], [r][k]
    uint32_t* Ws = qsm + 128 * QK_LD;     // [192][68], [n][k]  (transposed W)

    const int h    = blockIdx.y;
    const int row0 = blockIdx.x * 128;    // over B*T
    const int tid  = threadIdx.x;
    const int wid  = tid >> 5;
    const int lane = tid & 31;
    const int lrow = lane >> 2;           // 0..7
    const int lcol = lane & 3;            // 0..3

    const int warp_m = (wid & 1) * 64;    // 0 or 64
    const int warp_n = (wid >> 1) * 48;   // 0,48,96,144

#pragma unroll
    for (int it = 0; it < 8; it++) {
        const int i = it * 256 + tid;     // 0..2047 float4s
        const int r = i >> 4, c = (i & 15) * 4;
        const float4 v = *(const float4*)&x[(size_t)(row0 + r) * EE + h * HD + c];
        *(uint4*)&Xs[r * QK_LD + c] =
            make_uint4(f2tf32(v.x), f2tf32(v.y), f2tf32(v.z), f2tf32(v.w));
    }

    const float* Wh = Wq + (size_t)h * 64 * 192;
#pragma unroll
    for (int it = 0; it < 12; it++) {
        const int i = it * 256 + tid;     // 0..3071 float4s
        const int d = i / 48, c = (i % 48) * 4;
        const float4 v = *(const float4*)&Wh[d * 192 + c];
        Ws[(c + 0) * QK_LD + d] = f2tf32(v.x);
        Ws[(c + 1) * QK_LD + d] = f2tf32(v.y);
        Ws[(c + 2) * QK_LD + d] = f2tf32(v.z);
        Ws[(c + 3) * QK_LD + d] = f2tf32(v.w);
    }
    __syncthreads();

    float c[4][6][4];
#pragma unroll
    for (int m = 0; m < 4; m++)
#pragma unroll
        for (int n = 0; n < 6; n++)
#pragma unroll
            for (int f = 0; f < 4; f++) c[m][n][f] = 0.f;

#pragma unroll
    for (int ks = 0; ks < 8; ks++) {
        const int kk = ks * 8;
        uint32_t a[4][4], b[6][2];
#pragma unroll
        for (int m = 0; m < 4; m++) {
            const int ar = warp_m + m * 16 + lrow;
            a[m][0] = Xs[ar * QK_LD + kk + lcol];
            a[m][1] = Xs[(ar + 8) * QK_LD + kk + lcol];
            a[m][2] = Xs[ar * QK_LD + kk + 4 + lcol];
            a[m][3] = Xs[(ar + 8) * QK_LD + kk + 4 + lcol];
        }
#pragma unroll
        for (int n = 0; n < 6; n++) {
            const int br = warp_n + n * 8 + lrow;
            b[n][0] = Ws[br * QK_LD + kk + lcol];
            b[n][1] = Ws[br * QK_LD + kk + 4 + lcol];
        }
#pragma unroll
        for (int m = 0; m < 4; m++)
#pragma unroll
            for (int n = 0; n < 6; n++)
                mma_tf32_16x8x8(c[m][n][0], c[m][n][1], c[m][n][2], c[m][n][3],
                                a[m][0], a[m][1], a[m][2], a[m][3],
                                b[n][0], b[n][1]);
    }

    const float scale = (float)(1.0 / (8.0 + 1e-5));
#pragma unroll
    for (int n = 0; n < 6; n++) {
        const int col = warp_n + n * 8 + 2 * lcol;   // 0..191
        const int sec = col >> 6;                    // 0=q,1=k,2=v
        const int d   = col & 63;
        const float b0 = bq[h * 192 + col];
        const float b1 = bq[h * 192 + col + 1];
        float* dst = (sec == 0) ? g_Q : (sec == 1) ? g_K : g_V;
        const float mul = (sec == 0) ? scale : 1.0f;
#pragma unroll
        for (int m = 0; m < 4; m++) {
            const int r  = row0 + warp_m + m * 16 + lrow;
            const int b_ = r / TT;
            const int t  = r - b_ * TT;
            const size_t off = ((size_t)(b_ * HH + h) * TT + t) * HD + d;
            *(float2*)&dst[off] =
                make_float2((c[m][n][0] + b0) * mul, (c[m][n][1] + b1) * mul);
            const size_t off2 = off + (size_t)8 * HD;   // row r+8, same b_ (128 | TT)
            *(float2*)&dst[off2] =
                make_float2((c[m][n][2] + b0) * mul, (c[m][n][3] + b1) * mul);
        }
    }
}

// ---------------------------------------------------------------------------
// Kernel 2 (R12): tf32 mma.sync causal flash attention.
//   R7 shape (BM=64, 128 thr, occ 4) + in-place cp.async staging (no extra
//   smem, no extra regs), global big-first grid order, diagonal mma skip.
// ---------------------------------------------------------------------------
#define AT_LDQ 68   // Qs / P stride (uint32 elems)
#define AT_LDK 68   // Ks stride
#define AT_LDV 72   // Vs stride
#define AT_SMEM ((64 * AT_LDQ + 64 * AT_LDK + 64 * AT_LDV) * 4)   // 53248 B

__global__ __launch_bounds__(128, 4)
void attn_mma_kernel() {
    extern __shared__ uint32_t asm_[];
    uint32_t* Qs = asm_;                          // 64 x 68 (Q tile, later P)
    uint32_t* Ks = Qs + 64 * AT_LDQ;              // 64 x 68 raw fp32, [c][d]
    uint32_t* Vs = Ks + 64 * AT_LDK;              // 64 x 72 raw fp32, [c][d]

    const int bh = blockIdx.x;                    // bh on x
    const int qt = gridDim.y - 1 - blockIdx.y;    // ALL big tiles first chip-wide
    const int q0 = qt * 64;
    const float* Qp = g_Q + (size_t)bh * TT * HD;
    const float* Kp = g_K + (size_t)bh * TT * HD;
    const float* Vp = g_V + (size_t)bh * TT * HD;

    const int tid  = threadIdx.x;
    const int wid  = tid >> 5;
    const int lane = tid & 31;
    const int lrow = lane >> 2;    // 0..7
    const int lcol = lane & 3;     // 0..3
    const int wm   = wid * 16;     // warp's row base within tile

    const uint32_t smem_u32 = (uint32_t)__cvta_generic_to_shared(asm_);
    const uint32_t koff = smem_u32 + 64 * AT_LDQ * 4;
    const uint32_t voff = koff + 64 * AT_LDK * 4;

    // stage K or V tile kt via cp.async (raw fp32), one commit group each
    auto stage_k = [&](int kt) {
        const int kbase = kt * 64;
#pragma unroll
        for (int it = 0; it < 8; it++) {
            const int i = it * 128 + tid;          // 0..1023 float4s
            const int r = i >> 4, d = (i & 15) * 4;
            cp_async16(koff + (uint32_t)(r * AT_LDK + d) * 4,
                       Kp + (size_t)(kbase + r) * HD + d);
        }
        CP_COMMIT();
    };
    auto stage_v = [&](int kt) {
        const int kbase = kt * 64;
#pragma unroll
        for (int it = 0; it < 8; it++) {
            const int i = it * 128 + tid;
            const int r = i >> 4, d = (i & 15) * 4;
            cp_async16(voff + (uint32_t)(r * AT_LDV + d) * 4,
                       Vp + (size_t)(kbase + r) * HD + d);
        }
        CP_COMMIT();
    };

    // ---- start K0/V0 loads first, then stage Q while they fly ----
    stage_k(0);
    stage_v(0);

#pragma unroll
    for (int it = 0; it < 8; it++) {
        const int i = it * 512 + tid * 4;         // 0..4095
        const int r = i >> 6, d = i & 63;
        const float4 v = *(const float4*)&Qp[(size_t)(q0 + r) * HD + d];
        *(uint4*)&Qs[r * AT_LDQ + d] =
            make_uint4(f2tf32(v.x), f2tf32(v.y), f2tf32(v.z), f2tf32(v.w));
    }
    __syncthreads();

    uint32_t qf[8][4];
#pragma unroll
    for (int ks = 0; ks < 8; ks++) {
        const int base = (wm + lrow) * AT_LDQ + ks * 8 + lcol;
        qf[ks][0] = Qs[base];
        qf[ks][1] = Qs[base + 8 * AT_LDQ];
        qf[ks][2] = Qs[base + 4];
        qf[ks][3] = Qs[base + 8 * AT_LDQ + 4];
    }
    __syncthreads();   // Qs becomes the P buffer from here on

    float o[8][4];
#pragma unroll
    for (int n = 0; n < 8; n++)
#pragma unroll
        for (int f = 0; f < 4; f++) o[n][f] = 0.f;
    float m0 = -1e30f, m1 = -1e30f, l0 = 0.f, l1 = 0.f;

    const int r0g = q0 + wm + lrow;     // global row of frag-half 0
    const int r1g = r0g + 8;

    for (int kt = 0; kt <= qt; kt++) {
        const int kbase = kt * 64;
        // wait K(kt): it is the older of the (at most 2) pending groups
        CP_WAIT(1);
        __syncthreads();               // K(kt) visible to all warps

        // limit for diagonal tile: n/ks groups with col-min > warp row-max are
        // fully masked -> skip mma (bit-identical: P entries there are exact 0)
        const int hi = (kt == qt) ? ((wm + 15) >> 3) : 7;

        // ---- S = Q K^T (K raw fp32 -> cvt at fragment load) ----
        float s[8][4];
#pragma unroll
        for (int n = 0; n < 8; n++)
#pragma unroll
            for (int f = 0; f < 4; f++) s[n][f] = 0.f;

#pragma unroll
        for (int ks = 0; ks < 8; ks++) {
            const int kk = ks * 8;
#pragma unroll
            for (int n = 0; n < 8; n++) {
                if (n <= hi) {
                    const int kr = (n * 8 + lrow) * AT_LDK + kk + lcol;
                    const uint32_t b0 = f2tf32(__uint_as_float(Ks[kr]));
                    const uint32_t b1 = f2tf32(__uint_as_float(Ks[kr + 4]));
                    mma_tf32_16x8x8(s[n][0], s[n][1], s[n][2], s[n][3],
                                    qf[ks][0], qf[ks][1], qf[ks][2], qf[ks][3],
                                    b0, b1);
                }
            }
        }
        __syncthreads();               // all warps done reading Ks
        if (kt < qt) stage_k(kt + 1);  // overwrite Ks while we do softmax+PV

        if (kt == qt) {   // causal mask on diagonal tile (covers skipped tiles)
#pragma unroll
            for (int n = 0; n < 8; n++) {
                const int cg = kbase + n * 8 + 2 * lcol;
                if (cg     > r0g) s[n][0] = -1e30f;
                if (cg + 1 > r0g) s[n][1] = -1e30f;
                if (cg     > r1g) s[n][2] = -1e30f;
                if (cg + 1 > r1g) s[n][3] = -1e30f;
            }
        }

        // ---- online softmax (registers + quad shuffle) ----
        float mx0 = m0, mx1 = m1;
#pragma unroll
        for (int n = 0; n < 8; n++) {
            mx0 = fmaxf(mx0, fmaxf(s[n][0], s[n][1]));
            mx1 = fmaxf(mx1, fmaxf(s[n][2], s[n][3]));
        }
        mx0 = fmaxf(mx0, __shfl_xor_sync(0xffffffffu, mx0, 1));
        mx0 = fmaxf(mx0, __shfl_xor_sync(0xffffffffu, mx0, 2));
        mx1 = fmaxf(mx1, __shfl_xor_sync(0xffffffffu, mx1, 1));
        mx1 = fmaxf(mx1, __shfl_xor_sync(0xffffffffu, mx1, 2));

        float sum0 = 0.f, sum1 = 0.f;
#pragma unroll
        for (int n = 0; n < 8; n++) {
            s[n][0] = __expf(s[n][0] - mx0);
            s[n][1] = __expf(s[n][1] - mx0);
            s[n][2] = __expf(s[n][2] - mx1);
            s[n][3] = __expf(s[n][3] - mx1);
            sum0 += s[n][0] + s[n][1];
            sum1 += s[n][2] + s[n][3];
        }
        sum0 += __shfl_xor_sync(0xffffffffu, sum0, 1);
        sum0 += __shfl_xor_sync(0xffffffffu, sum0, 2);
        sum1 += __shfl_xor_sync(0xffffffffu, sum1, 1);
        sum1 += __shfl_xor_sync(0xffffffffu, sum1, 2);

        const float cf0 = __expf(m0 - mx0);
        const float cf1 = __expf(m1 - mx1);
        l0 = l0 * cf0 + sum0;  m0 = mx0;
        l1 = l1 * cf1 + sum1;  m1 = mx1;
#pragma unroll
        for (int n = 0; n < 8; n++) {
            o[n][0] *= cf0; o[n][1] *= cf0;
            o[n][2] *= cf1; o[n][3] *= cf1;
        }

        // wait V(kt): if K(kt+1) was just committed it is the newest pending
        if (kt < qt) { CP_WAIT(1); } else { CP_WAIT(0); }
        __syncthreads();               // V(kt) visible to all warps

        // ---- P -> smem (per-warp region of Qs), then PV (V cvt at load) ----
#pragma unroll
        for (int n = 0; n < 8; n++) {
            const int pr = (wm + lrow) * AT_LDQ + n * 8 + 2 * lcol;
            *(uint2*)&Qs[pr] = make_uint2(f2tf32(s[n][0]), f2tf32(s[n][1]));
            *(uint2*)&Qs[pr + 8 * AT_LDQ] = make_uint2(f2tf32(s[n][2]), f2tf32(s[n][3]));
        }
        __syncwarp();

#pragma unroll
        for (int ks = 0; ks < 8; ks++) {
            if (ks <= hi) {
                const int kk = ks * 8;
                const int pb = (wm + lrow) * AT_LDQ + kk + lcol;
                const uint32_t a0 = Qs[pb];
                const uint32_t a1 = Qs[pb + 8 * AT_LDQ];
                const uint32_t a2 = Qs[pb + 4];
                const uint32_t a3 = Qs[pb + 8 * AT_LDQ + 4];
#pragma unroll
                for (int n = 0; n < 8; n++) {
                    const uint32_t b0 = f2tf32(__uint_as_float(Vs[(kk + lcol) * AT_LDV + n * 8 + lrow]));
                    const uint32_t b1 = f2tf32(__uint_as_float(Vs[(kk + 4 + lcol) * AT_LDV + n * 8 + lrow]));
                    mma_tf32_16x8x8(o[n][0], o[n][1], o[n][2], o[n][3],
                                    a0, a1, a2, a3, b0, b1);
                }
            }
        }
        __syncthreads();               // all warps done reading Vs
        if (kt < qt) stage_v(kt + 1);  // overwrite Vs; lands during next QK
    }

    // ---- normalize and store ----
    const float inv0 = 1.0f / l0;
    const float inv1 = 1.0f / l1;
    const int b_ = bh >> 4, h = bh & 15;
    const size_t rowbase0 = (size_t)(b_ * TT + r0g) * EE + h * HD;
    const size_t rowbase1 = (size_t)(b_ * TT + r1g) * EE + h * HD;
#pragma unroll
    for (int n = 0; n < 8; n++) {
        const int d = n * 8 + 2 * lcol;
        *(float2*)&g_AO[rowbase0 + d] = make_float2(o[n][0] * inv0, o[n][1] * inv0);
        *(float2*)&g_AO[rowbase1 + d] = make_float2(o[n][2] * inv1, o[n][3] * inv1);
    }
}

// ---------------------------------------------------------------------------
// Kernel 3: tf32 mma.sync output projection, cp.async double-buffered
// (unchanged from R11 — known correct, 16 warps/SM register-bound)
// ---------------------------------------------------------------------------
#define PJ_LDA 36   // 32 + 4 pad (float4-aligned, conflict-free fragments)
#define PJ_SMEM (4 * 128 * PJ_LDA * 4)   // 73728 B

__global__ __launch_bounds__(256)
void proj_mma_kernel(const float* __restrict__ Wp,
                     const float* __restrict__ bp,
                     float* __restrict__ out) {
    extern __shared__ uint32_t psm[];
    uint32_t* Ab[2] = { psm,                  psm + 2 * 128 * PJ_LDA };
    uint32_t* Bb[2] = { psm + 128 * PJ_LDA,   psm + 3 * 128 * PJ_LDA };

    const int tid  = threadIdx.x;
    const int wid  = tid >> 5;
    const int lane = tid & 31;
    const int row0 = blockIdx.x * 128;
    const int col0 = blockIdx.y * 128;

    const uint32_t smem_u32 = (uint32_t)__cvta_generic_to_shared(psm);
    const uint32_t aoff[2] = { smem_u32,                         smem_u32 + 2 * 128 * PJ_LDA * 4 };
    const uint32_t boff[2] = { smem_u32 + 128 * PJ_LDA * 4,      smem_u32 + 3 * 128 * PJ_LDA * 4 };

    const int warp_m = (wid & 1) * 64;   // 0 or 64
    const int warp_n = (wid >> 1) * 32;  // 0,32,64,96

    auto stage = [&](int kt, int buf) {
        const int k0 = kt * 32;
#pragma unroll
        for (int it = 0; it < 4; it++) {
            const int lin = it * 1024 + tid * 4;   // 0..4095
            const int r = lin >> 5, cc = lin & 31;
            cp_async16(aoff[buf] + (uint32_t)(r * PJ_LDA + cc) * 4,
                       &g_AO[(size_t)(row0 + r) * EE + k0 + cc]);
            cp_async16(boff[buf] + (uint32_t)(r * PJ_LDA + cc) * 4,
                       &Wp[(size_t)(col0 + r) * EE + k0 + cc]);
        }
        CP_COMMIT();
    };

    float c[4][4][4];   // [m16][n8][frag]
#pragma unroll
    for (int m = 0; m < 4; m++)
#pragma unroll
        for (int n = 0; n < 4; n++)
#pragma unroll
            for (int f = 0; f < 4; f++) c[m][n][f] = 0.f;

    const int lrow = lane >> 2;    // 0..7
    const int lcol = lane & 3;     // 0..3

    stage(0, 0);
    stage(1, 1);

    for (int kt = 0; kt < EE / 32; kt++) {
        if (kt < EE / 32 - 1) { CP_WAIT(1); } else { CP_WAIT(0); }
        __syncthreads();
        const int cur = kt & 1;
        const uint32_t* As = Ab[cur];
        const uint32_t* Bs = Bb[cur];

#pragma unroll
        for (int ks = 0; ks < 4; ks++) {
            const int kk = ks * 8;
            uint32_t a[4][4], b[4][2];
#pragma unroll
            for (int m = 0; m < 4; m++) {
                const int ar = warp_m + m * 16 + lrow;
                a[m][0] = f2tf32(__uint_as_float(As[ar * PJ_LDA + kk + lcol]));
                a[m][1] = f2tf32(__uint_as_float(As[(ar + 8) * PJ_LDA + kk + lcol]));
                a[m][2] = f2tf32(__uint_as_float(As[ar * PJ_LDA + kk + 4 + lcol]));
                a[m][3] = f2tf32(__uint_as_float(As[(ar + 8) * PJ_LDA + kk + 4 + lcol]));
            }
#pragma unroll
            for (int n = 0; n < 4; n++) {
                const int br = warp_n + n * 8 + lrow;
                b[n][0] = f2tf32(__uint_as_float(Bs[br * PJ_LDA + kk + lcol]));
                b[n][1] = f2tf32(__uint_as_float(Bs[br * PJ_LDA + kk + 4 + lcol]));
            }
#pragma unroll
            for (int m = 0; m < 4; m++)
#pragma unroll
                for (int n = 0; n < 4; n++)
                    mma_tf32_16x8x8(c[m][n][0], c[m][n][1], c[m][n][2], c[m][n][3],
                                    a[m][0], a[m][1], a[m][2], a[m][3],
                                    b[n][0], b[n][1]);
        }

        __syncthreads();   // all warps done reading buf[cur] before refill
        if (kt + 2 < EE / 32) stage(kt + 2, cur);
    }

#pragma unroll
    for (int m = 0; m < 4; m++) {
#pragma unroll
        for (int n = 0; n < 4; n++) {
            const int col = col0 + warp_n + n * 8 + 2 * lcol;
            const int r1  = row0 + warp_m + m * 16 + lrow;
            const float b0 = bp[col], b1 = bp[col + 1];
            float2 o0 = make_float2(c[m][n][0] + b0, c[m][n][1] + b1);
            float2 o1 = make_float2(c[m][n][2] + b0, c[m][n][3] + b1);
            *(float2*)&out[(size_t)r1 * EE + col]       = o0;
            *(float2*)&out[(size_t)(r1 + 8) * EE + col] = o1;
        }
    }
}

// ---------------------------------------------------------------------------
// Launch
// ---------------------------------------------------------------------------
extern "C" void kernel_launch(void* const* d_in, const int* in_sizes, int n_in,
                              void* d_out, int out_size) {
    const float* x  = (const float*)d_in[0];
    const float* Wq = (const float*)d_in[1];
    const float* bq = (const float*)d_in[2];
    const float* Wp = (const float*)d_in[3];
    const float* bp = (const float*)d_in[4];
    float* out = (float*)d_out;

    cudaFuncSetAttribute(qkv_mma_kernel,  cudaFuncAttributeMaxDynamicSharedMemorySize, QK_SMEM);
    cudaFuncSetAttribute(attn_mma_kernel, cudaFuncAttributeMaxDynamicSharedMemorySize, AT_SMEM);
    cudaFuncSetAttribute(proj_mma_kernel, cudaFuncAttributeMaxDynamicSharedMemorySize, PJ_SMEM);

    qkv_mma_kernel<<<dim3(BT / 128, HH), 256, QK_SMEM>>>(x, Wq, bq);
    // bh on x, tile on y: all longest CTAs chip-wide launch first
    attn_mma_kernel<<<dim3(BB * HH, TT / 64), 128, AT_SMEM>>>();
    proj_mma_kernel<<<dim3(BT / 128, EE / 128), 256, PJ_SMEM>>>(Wp, bp, out);
}

// round 14
// speedup vs baseline: 1.4516x; 1.4479x over previous
#include <cuda_runtime.h>
#include <cuda_fp16.h>
#include <cstdint>

// Problem constants
#define BB 4
#define TT 2048
#define EE 1024
#define HH 16
#define HD 64
#define BT (BB * TT)   // 8192 rows

// ---------------------------------------------------------------------------
// Scratch (static __device__ arrays; no runtime allocation allowed)
// ---------------------------------------------------------------------------
__device__ float g_Q[BB * HH * TT * HD];   // [b,h,t,d], q pre-scaled
__device__ float g_K[BB * HH * TT * HD];
__device__ float g_V[BB * HH * TT * HD];
__device__ float g_AO[BT * EE];            // attention output, [b,t,e]

// ---------------------------------------------------------------------------
// tf32 / fp16 / cp.async helpers (all sm_80+ PTX — valid at plain sm_100)
// ---------------------------------------------------------------------------
__device__ __forceinline__ uint32_t f2tf32(float f) {
    uint32_t r;
    asm("cvt.rna.tf32.f32 %0, %1;" : "=r"(r) : "f"(f));
    return r;
}

__device__ __forceinline__ uint32_t pack_h2(float lo, float hi) {
    __half2 h = __floats2half2_rn(lo, hi);
    return *reinterpret_cast<uint32_t*>(&h);
}

__device__ __forceinline__ void mma_tf32_16x8x8(
    float& c0, float& c1, float& c2, float& c3,
    uint32_t a0, uint32_t a1, uint32_t a2, uint32_t a3,
    uint32_t b0, uint32_t b1) {
    asm volatile(
        "mma.sync.aligned.m16n8k8.row.col.f32.tf32.tf32.f32 "
        "{%0,%1,%2,%3}, {%4,%5,%6,%7}, {%8,%9}, {%0,%1,%2,%3};"
        : "+f"(c0), "+f"(c1), "+f"(c2), "+f"(c3)
        : "r"(a0), "r"(a1), "r"(a2), "r"(a3), "r"(b0), "r"(b1));
}

// fp16 inputs, fp32 accumulate, K=16
__device__ __forceinline__ void mma_f16_16x8x16(
    float& c0, float& c1, float& c2, float& c3,
    uint32_t a0, uint32_t a1, uint32_t a2, uint32_t a3,
    uint32_t b0, uint32_t b1) {
    asm volatile(
        "mma.sync.aligned.m16n8k16.row.col.f32.f16.f16.f32 "
        "{%0,%1,%2,%3}, {%4,%5,%6,%7}, {%8,%9}, {%0,%1,%2,%3};"
        : "+f"(c0), "+f"(c1), "+f"(c2), "+f"(c3)
        : "r"(a0), "r"(a1), "r"(a2), "r"(a3), "r"(b0), "r"(b1));
}

__device__ __forceinline__ void ldmatrix_x2_trans(uint32_t& r0, uint32_t& r1,
                                                  uint32_t smem_addr) {
    asm volatile("ldmatrix.sync.aligned.m8n8.x2.trans.shared.b16 {%0,%1}, [%2];"
                 : "=r"(r0), "=r"(r1) : "r"(smem_addr));
}

__device__ __forceinline__ void cp_async16(uint32_t dst_smem, const void* src) {
    asm volatile("cp.async.cg.shared.global [%0], [%1], 16;"
                 :: "r"(dst_smem), "l"(src));
}
#define CP_COMMIT() asm volatile("cp.async.commit_group;" ::: "memory")
#define CP_WAIT(N)  asm volatile("cp.async.wait_group %0;" :: "n"(N) : "memory")

// ---------------------------------------------------------------------------
// Kernel 1: tf32 mma.sync per-head QKV projection (unchanged — known correct)
// ---------------------------------------------------------------------------
#define QK_LD   68
#define QK_SMEM ((128 * QK_LD + 192 * QK_LD) * 4)   // 87040 B (dynamic)

__global__ __launch_bounds__(256, 1)
void qkv_mma_kernel(const float* __restrict__ x,
                    const float* __restrict__ Wq,
                    const float* __restrict__ bq) {
    extern __shared__ uint32_t qsm[];
    uint32_t* Xs = qsm;                   // [128][68], [r][k]
    uint32_t* Ws = qsm + 128 * QK_LD;     // [192][68], [n][k]  (transposed W)

    const int h    = blockIdx.y;
    const int row0 = blockIdx.x * 128;    // over B*T
    const int tid  = threadIdx.x;
    const int wid  = tid >> 5;
    const int lane = tid & 31;
    const int lrow = lane >> 2;           // 0..7
    const int lcol = lane & 3;            // 0..3

    const int warp_m = (wid & 1) * 64;    // 0 or 64
    const int warp_n = (wid >> 1) * 48;   // 0,48,96,144

#pragma unroll
    for (int it = 0; it < 8; it++) {
        const int i = it * 256 + tid;     // 0..2047 float4s
        const int r = i >> 4, c = (i & 15) * 4;
        const float4 v = *(const float4*)&x[(size_t)(row0 + r) * EE + h * HD + c];
        *(uint4*)&Xs[r * QK_LD + c] =
            make_uint4(f2tf32(v.x), f2tf32(v.y), f2tf32(v.z), f2tf32(v.w));
    }

    const float* Wh = Wq + (size_t)h * 64 * 192;
#pragma unroll
    for (int it = 0; it < 12; it++) {
        const int i = it * 256 + tid;     // 0..3071 float4s
        const int d = i / 48, c = (i % 48) * 4;
        const float4 v = *(const float4*)&Wh[d * 192 + c];
        Ws[(c + 0) * QK_LD + d] = f2tf32(v.x);
        Ws[(c + 1) * QK_LD + d] = f2tf32(v.y);
        Ws[(c + 2) * QK_LD + d] = f2tf32(v.z);
        Ws[(c + 3) * QK_LD + d] = f2tf32(v.w);
    }
    __syncthreads();

    float c[4][6][4];
#pragma unroll
    for (int m = 0; m < 4; m++)
#pragma unroll
        for (int n = 0; n < 6; n++)
#pragma unroll
            for (int f = 0; f < 4; f++) c[m][n][f] = 0.f;

#pragma unroll
    for (int ks = 0; ks < 8; ks++) {
        const int kk = ks * 8;
        uint32_t a[4][4], b[6][2];
#pragma unroll
        for (int m = 0; m < 4; m++) {
            const int ar = warp_m + m * 16 + lrow;
            a[m][0] = Xs[ar * QK_LD + kk + lcol];
            a[m][1] = Xs[(ar + 8) * QK_LD + kk + lcol];
            a[m][2] = Xs[ar * QK_LD + kk + 4 + lcol];
            a[m][3] = Xs[(ar + 8) * QK_LD + kk + 4 + lcol];
        }
#pragma unroll
        for (int n = 0; n < 6; n++) {
            const int br = warp_n + n * 8 + lrow;
            b[n][0] = Ws[br * QK_LD + kk + lcol];
            b[n][1] = Ws[br * QK_LD + kk + 4 + lcol];
        }
#pragma unroll
        for (int m = 0; m < 4; m++)
#pragma unroll
            for (int n = 0; n < 6; n++)
                mma_tf32_16x8x8(c[m][n][0], c[m][n][1], c[m][n][2], c[m][n][3],
                                a[m][0], a[m][1], a[m][2], a[m][3],
                                b[n][0], b[n][1]);
    }

    const float scale = (float)(1.0 / (8.0 + 1e-5));
#pragma unroll
    for (int n = 0; n < 6; n++) {
        const int col = warp_n + n * 8 + 2 * lcol;   // 0..191
        const int sec = col >> 6;                    // 0=q,1=k,2=v
        const int d   = col & 63;
        const float b0 = bq[h * 192 + col];
        const float b1 = bq[h * 192 + col + 1];
        float* dst = (sec == 0) ? g_Q : (sec == 1) ? g_K : g_V;
        const float mul = (sec == 0) ? scale : 1.0f;
#pragma unroll
        for (int m = 0; m < 4; m++) {
            const int r  = row0 + warp_m + m * 16 + lrow;
            const int b_ = r / TT;
            const int t  = r - b_ * TT;
            const size_t off = ((size_t)(b_ * HH + h) * TT + t) * HD + d;
            *(float2*)&dst[off] =
                make_float2((c[m][n][0] + b0) * mul, (c[m][n][1] + b1) * mul);
            const size_t off2 = off + (size_t)8 * HD;   // row r+8, same b_ (128 | TT)
            *(float2*)&dst[off2] =
                make_float2((c[m][n][2] + b0) * mul, (c[m][n][3] + b1) * mul);
        }
    }
}

// ---------------------------------------------------------------------------
// Kernel 2 (R14): fp16 mma.m16n8k16 causal flash attention.
//   R7 loop structure verbatim (BM=64, 128 thr, occ 4, sync staging, grid
//   (TT/64, BB*HH)); only the datapath changes: Q/K/P/V held as fp16x2 in
//   smem, K=16 mma (half the mma+LDS count), V B-frags via ldmatrix.x2.trans.
//   smem 27.6 KB (was 53 KB).
// ---------------------------------------------------------------------------
#define AT_P    36                              // uint32 (fp16x2) row stride
#define AT_SMEM (3 * 64 * AT_P * 4)             // 27648 B

__global__ __launch_bounds__(128, 4)
void attn_mma_kernel() {
    extern __shared__ uint32_t asm_[];
    uint32_t* Qs = asm_;                  // [64][36] fp16x2: Q tile, later P
    uint32_t* Ks = Qs + 64 * AT_P;        // [64][36] fp16x2: K, [c][d-pairs]
    uint32_t* Vs = Ks + 64 * AT_P;        // [64][36] fp16x2: V, [k][d-pairs]

    const int bh = blockIdx.y;
    const int qt = gridDim.x - 1 - blockIdx.x;    // big tiles first
    const int q0 = qt * 64;
    const float* Qp = g_Q + (size_t)bh * TT * HD;
    const float* Kp = g_K + (size_t)bh * TT * HD;
    const float* Vp = g_V + (size_t)bh * TT * HD;

    const int tid  = threadIdx.x;
    const int wid  = tid >> 5;
    const int lane = tid & 31;
    const int lrow = lane >> 2;    // 0..7
    const int lcol = lane & 3;     // 0..3
    const int wm   = wid * 16;     // warp's row base within tile

    const uint32_t smem_u32 = (uint32_t)__cvta_generic_to_shared(asm_);
    // per-lane ldmatrix row base inside Vs: row (lane&15), row stride 144 B
    const uint32_t v_row_addr = smem_u32 + (2 * 64 * AT_P) * 4
                              + (uint32_t)(lane & 15) * (AT_P * 4);

    // ---- stage Q tile (fp16x2) and load fragments into registers ----
#pragma unroll
    for (int it = 0; it < 8; it++) {
        const int i = it * 512 + tid * 4;         // 0..4095
        const int r = i >> 6, d = i & 63;
        const float4 v = *(const float4*)&Qp[(size_t)(q0 + r) * HD + d];
        *(uint2*)&Qs[r * AT_P + (d >> 1)] =
            make_uint2(pack_h2(v.x, v.y), pack_h2(v.z, v.w));
    }
    __syncthreads();

    uint32_t qf[4][4];   // 4 k-steps of 16
#pragma unroll
    for (int ks = 0; ks < 4; ks++) {
        const int base = (wm + lrow) * AT_P + ks * 8 + lcol;
        qf[ks][0] = Qs[base];
        qf[ks][1] = Qs[base + 8 * AT_P];
        qf[ks][2] = Qs[base + 4];
        qf[ks][3] = Qs[base + 8 * AT_P + 4];
    }
    __syncthreads();   // Qs becomes the P buffer from here on

    float o[8][4];
#pragma unroll
    for (int n = 0; n < 8; n++)
#pragma unroll
        for (int f = 0; f < 4; f++) o[n][f] = 0.f;
    float m0 = -1e30f, m1 = -1e30f, l0 = 0.f, l1 = 0.f;

    const int r0g = q0 + wm + lrow;     // global row of frag-half 0
    const int r1g = r0g + 8;

    for (int kt = 0; kt <= qt; kt++) {
        const int kbase = kt * 64;
        __syncthreads();               // prev PV done with Ks/Vs
#pragma unroll
        for (int it = 0; it < 8; it++) {
            const int i = it * 512 + tid * 4;
            const int r = i >> 6, d = i & 63;
            const float4 kv = *(const float4*)&Kp[(size_t)(kbase + r) * HD + d];
            const float4 vv = *(const float4*)&Vp[(size_t)(kbase + r) * HD + d];
            *(uint2*)&Ks[r * AT_P + (d >> 1)] =
                make_uint2(pack_h2(kv.x, kv.y), pack_h2(kv.z, kv.w));
            *(uint2*)&Vs[r * AT_P + (d >> 1)] =
                make_uint2(pack_h2(vv.x, vv.y), pack_h2(vv.z, vv.w));
        }
        __syncthreads();

        // ---- S = Q K^T (fp16, K=16 per mma) ----
        float s[8][4];
#pragma unroll
        for (int n = 0; n < 8; n++)
#pragma unroll
            for (int f = 0; f < 4; f++) s[n][f] = 0.f;

#pragma unroll
        for (int ks = 0; ks < 4; ks++) {
#pragma unroll
            for (int n = 0; n < 8; n++) {
                const int kr = (n * 8 + lrow) * AT_P + ks * 8 + lcol;
                const uint32_t b0 = Ks[kr];
                const uint32_t b1 = Ks[kr + 4];
                mma_f16_16x8x16(s[n][0], s[n][1], s[n][2], s[n][3],
                                qf[ks][0], qf[ks][1], qf[ks][2], qf[ks][3],
                                b0, b1);
            }
        }

        if (kt == qt) {   // causal mask on diagonal tile
#pragma unroll
            for (int n = 0; n < 8; n++) {
                const int cg = kbase + n * 8 + 2 * lcol;
                if (cg     > r0g) s[n][0] = -1e30f;
                if (cg + 1 > r0g) s[n][1] = -1e30f;
                if (cg     > r1g) s[n][2] = -1e30f;
                if (cg + 1 > r1g) s[n][3] = -1e30f;
            }
        }

        // ---- online softmax (registers + quad shuffle) ----
        float mx0 = m0, mx1 = m1;
#pragma unroll
        for (int n = 0; n < 8; n++) {
            mx0 = fmaxf(mx0, fmaxf(s[n][0], s[n][1]));
            mx1 = fmaxf(mx1, fmaxf(s[n][2], s[n][3]));
        }
        mx0 = fmaxf(mx0, __shfl_xor_sync(0xffffffffu, mx0, 1));
        mx0 = fmaxf(mx0, __shfl_xor_sync(0xffffffffu, mx0, 2));
        mx1 = fmaxf(mx1, __shfl_xor_sync(0xffffffffu, mx1, 1));
        mx1 = fmaxf(mx1, __shfl_xor_sync(0xffffffffu, mx1, 2));

        float sum0 = 0.f, sum1 = 0.f;
#pragma unroll
        for (int n = 0; n < 8; n++) {
            s[n][0] = __expf(s[n][0] - mx0);
            s[n][1] = __expf(s[n][1] - mx0);
            s[n][2] = __expf(s[n][2] - mx1);
            s[n][3] = __expf(s[n][3] - mx1);
            sum0 += s[n][0] + s[n][1];
            sum1 += s[n][2] + s[n][3];
        }
        sum0 += __shfl_xor_sync(0xffffffffu, sum0, 1);
        sum0 += __shfl_xor_sync(0xffffffffu, sum0, 2);
        sum1 += __shfl_xor_sync(0xffffffffu, sum1, 1);
        sum1 += __shfl_xor_sync(0xffffffffu, sum1, 2);

        const float cf0 = __expf(m0 - mx0);
        const float cf1 = __expf(m1 - mx1);
        l0 = l0 * cf0 + sum0;  m0 = mx0;
        l1 = l1 * cf1 + sum1;  m1 = mx1;
#pragma unroll
        for (int n = 0; n < 8; n++) {
            o[n][0] *= cf0; o[n][1] *= cf0;
            o[n][2] *= cf1; o[n][3] *= cf1;
        }

        // ---- P -> per-warp fp16x2 smem rows, then PV ----
#pragma unroll
        for (int n = 0; n < 8; n++) {
            const int pr = (wm + lrow) * AT_P + n * 4 + lcol;
            Qs[pr]            = pack_h2(s[n][0], s[n][1]);
            Qs[pr + 8 * AT_P] = pack_h2(s[n][2], s[n][3]);
        }
        __syncwarp();

#pragma unroll
        for (int ks = 0; ks < 4; ks++) {
            const int pb = (wm + lrow) * AT_P + ks * 8 + lcol;
            const uint32_t a0 = Qs[pb];
            const uint32_t a1 = Qs[pb + 8 * AT_P];
            const uint32_t a2 = Qs[pb + 4];
            const uint32_t a3 = Qs[pb + 8 * AT_P + 4];
            const uint32_t vk = v_row_addr + (uint32_t)(ks * 16 * AT_P * 4);
#pragma unroll
            for (int n = 0; n < 8; n++) {
                uint32_t b0, b1;
                ldmatrix_x2_trans(b0, b1, vk + (uint32_t)(n * 16));
                mma_f16_16x8x16(o[n][0], o[n][1], o[n][2], o[n][3],
                                a0, a1, a2, a3, b0, b1);
            }
        }
        __syncwarp();
    }

    // ---- normalize and store ----
    const float inv0 = 1.0f / l0;
    const float inv1 = 1.0f / l1;
    const int b_ = bh >> 4, h = bh & 15;
    const size_t rowbase0 = (size_t)(b_ * TT + r0g) * EE + h * HD;
    const size_t rowbase1 = (size_t)(b_ * TT + r1g) * EE + h * HD;
#pragma unroll
    for (int n = 0; n < 8; n++) {
        const int d = n * 8 + 2 * lcol;
        *(float2*)&g_AO[rowbase0 + d] = make_float2(o[n][0] * inv0, o[n][1] * inv0);
        *(float2*)&g_AO[rowbase1 + d] = make_float2(o[n][2] * inv1, o[n][3] * inv1);
    }
}

// ---------------------------------------------------------------------------
// Kernel 3: tf32 mma.sync output projection, cp.async double-buffered
// (unchanged from R11 — known correct, 16 warps/SM register-bound)
// ---------------------------------------------------------------------------
#define PJ_LDA 36   // 32 + 4 pad (float4-aligned, conflict-free fragments)
#define PJ_SMEM (4 * 128 * PJ_LDA * 4)   // 73728 B

__global__ __launch_bounds__(256)
void proj_mma_kernel(const float* __restrict__ Wp,
                     const float* __restrict__ bp,
                     float* __restrict__ out) {
    extern __shared__ uint32_t psm[];
    uint32_t* Ab[2] = { psm,                  psm + 2 * 128 * PJ_LDA };
    uint32_t* Bb[2] = { psm + 128 * PJ_LDA,   psm + 3 * 128 * PJ_LDA };

    const int tid  = threadIdx.x;
    const int wid  = tid >> 5;
    const int lane = tid & 31;
    const int row0 = blockIdx.x * 128;
    const int col0 = blockIdx.y * 128;

    const uint32_t smem_u32 = (uint32_t)__cvta_generic_to_shared(psm);
    const uint32_t aoff[2] = { smem_u32,                         smem_u32 + 2 * 128 * PJ_LDA * 4 };
    const uint32_t boff[2] = { smem_u32 + 128 * PJ_LDA * 4,      smem_u32 + 3 * 128 * PJ_LDA * 4 };

    const int warp_m = (wid & 1) * 64;   // 0 or 64
    const int warp_n = (wid >> 1) * 32;  // 0,32,64,96

    auto stage = [&](int kt, int buf) {
        const int k0 = kt * 32;
#pragma unroll
        for (int it = 0; it < 4; it++) {
            const int lin = it * 1024 + tid * 4;   // 0..4095
            const int r = lin >> 5, cc = lin & 31;
            cp_async16(aoff[buf] + (uint32_t)(r * PJ_LDA + cc) * 4,
                       &g_AO[(size_t)(row0 + r) * EE + k0 + cc]);
            cp_async16(boff[buf] + (uint32_t)(r * PJ_LDA + cc) * 4,
                       &Wp[(size_t)(col0 + r) * EE + k0 + cc]);
        }
        CP_COMMIT();
    };

    float c[4][4][4];   // [m16][n8][frag]
#pragma unroll
    for (int m = 0; m < 4; m++)
#pragma unroll
        for (int n = 0; n < 4; n++)
#pragma unroll
            for (int f = 0; f < 4; f++) c[m][n][f] = 0.f;

    const int lrow = lane >> 2;    // 0..7
    const int lcol = lane & 3;     // 0..3

    stage(0, 0);
    stage(1, 1);

    for (int kt = 0; kt < EE / 32; kt++) {
        if (kt < EE / 32 - 1) { CP_WAIT(1); } else { CP_WAIT(0); }
        __syncthreads();
        const int cur = kt & 1;
        const uint32_t* As = Ab[cur];
        const uint32_t* Bs = Bb[cur];

#pragma unroll
        for (int ks = 0; ks < 4; ks++) {
            const int kk = ks * 8;
            uint32_t a[4][4], b[4][2];
#pragma unroll
            for (int m = 0; m < 4; m++) {
                const int ar = warp_m + m * 16 + lrow;
                a[m][0] = f2tf32(__uint_as_float(As[ar * PJ_LDA + kk + lcol]));
                a[m][1] = f2tf32(__uint_as_float(As[(ar + 8) * PJ_LDA + kk + lcol]));
                a[m][2] = f2tf32(__uint_as_float(As[ar * PJ_LDA + kk + 4 + lcol]));
                a[m][3] = f2tf32(__uint_as_float(As[(ar + 8) * PJ_LDA + kk + 4 + lcol]));
            }
#pragma unroll
            for (int n = 0; n < 4; n++) {
                const int br = warp_n + n * 8 + lrow;
                b[n][0] = f2tf32(__uint_as_float(Bs[br * PJ_LDA + kk + lcol]));
                b[n][1] = f2tf32(__uint_as_float(Bs[br * PJ_LDA + kk + 4 + lcol]));
            }
#pragma unroll
            for (int m = 0; m < 4; m++)
#pragma unroll
                for (int n = 0; n < 4; n++)
                    mma_tf32_16x8x8(c[m][n][0], c[m][n][1], c[m][n][2], c[m][n][3],
                                    a[m][0], a[m][1], a[m][2], a[m][3],
                                    b[n][0], b[n][1]);
        }

        __syncthreads();   // all warps done reading buf[cur] before refill
        if (kt + 2 < EE / 32) stage(kt + 2, cur);
    }

#pragma unroll
    for (int m = 0; m < 4; m++) {
#pragma unroll
        for (int n = 0; n < 4; n++) {
            const int col = col0 + warp_n + n * 8 + 2 * lcol;
            const int r1  = row0 + warp_m + m * 16 + lrow;
            const float b0 = bp[col], b1 = bp[col + 1];
            float2 o0 = make_float2(c[m][n][0] + b0, c[m][n][1] + b1);
            float2 o1 = make_float2(c[m][n][2] + b0, c[m][n][3] + b1);
            *(float2*)&out[(size_t)r1 * EE + col]       = o0;
            *(float2*)&out[(size_t)(r1 + 8) * EE + col] = o1;
        }
    }
}

// ---------------------------------------------------------------------------
// Launch
// ---------------------------------------------------------------------------
extern "C" void kernel_launch(void* const* d_in, const int* in_sizes, int n_in,
                              void* d_out, int out_size) {
    const float* x  = (const float*)d_in[0];
    const float* Wq = (const float*)d_in[1];
    const float* bq = (const float*)d_in[2];
    const float* Wp = (const float*)d_in[3];
    const float* bp = (const float*)d_in[4];
    float* out = (float*)d_out;

    cudaFuncSetAttribute(qkv_mma_kernel,  cudaFuncAttributeMaxDynamicSharedMemorySize, QK_SMEM);
    cudaFuncSetAttribute(attn_mma_kernel, cudaFuncAttributeMaxDynamicSharedMemorySize, AT_SMEM);
    cudaFuncSetAttribute(proj_mma_kernel, cudaFuncAttributeMaxDynamicSharedMemorySize, PJ_SMEM);

    qkv_mma_kernel<<<dim3(BT / 128, HH), 256, QK_SMEM>>>(x, Wq, bq);
    attn_mma_kernel<<<dim3(TT / 64, BB * HH), 128, AT_SMEM>>>();
    proj_mma_kernel<<<dim3(BT / 128, EE / 128), 256, PJ_SMEM>>>(Wp, bp, out);
}

// round 15
// speedup vs baseline: 1.5224x; 1.0487x over previous
#include <cuda_runtime.h>
#include <cuda_fp16.h>
#include <cstdint>

// Problem constants
#define BB 4
#define TT 2048
#define EE 1024
#define HH 16
#define HD 64
#define BT (BB * TT)   // 8192 rows

// ---------------------------------------------------------------------------
// Scratch (static __device__ arrays; no runtime allocation allowed)
// Q/K/V stored as fp16 (rounded once in qkv epilogue — same rounding point
// as R14's stage-time pack, so attention numerics are bit-identical).
// ---------------------------------------------------------------------------
__device__ __half g_Q[BB * HH * TT * HD];   // [b,h,t,d], q pre-scaled
__device__ __half g_K[BB * HH * TT * HD];
__device__ __half g_V[BB * HH * TT * HD];
__device__ float  g_AO[BT * EE];            // attention output, [b,t,e]

// ---------------------------------------------------------------------------
// tf32 / fp16 / cp.async helpers (all sm_80+ PTX — valid at plain sm_100)
// ---------------------------------------------------------------------------
__device__ __forceinline__ uint32_t f2tf32(float f) {
    uint32_t r;
    asm("cvt.rna.tf32.f32 %0, %1;" : "=r"(r) : "f"(f));
    return r;
}

__device__ __forceinline__ uint32_t pack_h2(float lo, float hi) {
    __half2 h = __floats2half2_rn(lo, hi);
    return *reinterpret_cast<uint32_t*>(&h);
}

__device__ __forceinline__ void mma_tf32_16x8x8(
    float& c0, float& c1, float& c2, float& c3,
    uint32_t a0, uint32_t a1, uint32_t a2, uint32_t a3,
    uint32_t b0, uint32_t b1) {
    asm volatile(
        "mma.sync.aligned.m16n8k8.row.col.f32.tf32.tf32.f32 "
        "{%0,%1,%2,%3}, {%4,%5,%6,%7}, {%8,%9}, {%0,%1,%2,%3};"
        : "+f"(c0), "+f"(c1), "+f"(c2), "+f"(c3)
        : "r"(a0), "r"(a1), "r"(a2), "r"(a3), "r"(b0), "r"(b1));
}

// fp16 inputs, fp32 accumulate, K=16
__device__ __forceinline__ void mma_f16_16x8x16(
    float& c0, float& c1, float& c2, float& c3,
    uint32_t a0, uint32_t a1, uint32_t a2, uint32_t a3,
    uint32_t b0, uint32_t b1) {
    asm volatile(
        "mma.sync.aligned.m16n8k16.row.col.f32.f16.f16.f32 "
        "{%0,%1,%2,%3}, {%4,%5,%6,%7}, {%8,%9}, {%0,%1,%2,%3};"
        : "+f"(c0), "+f"(c1), "+f"(c2), "+f"(c3)
        : "r"(a0), "r"(a1), "r"(a2), "r"(a3), "r"(b0), "r"(b1));
}

__device__ __forceinline__ void ldmatrix_x2_trans(uint32_t& r0, uint32_t& r1,
                                                  uint32_t smem_addr) {
    asm volatile("ldmatrix.sync.aligned.m8n8.x2.trans.shared.b16 {%0,%1}, [%2];"
                 : "=r"(r0), "=r"(r1) : "r"(smem_addr));
}

__device__ __forceinline__ void cp_async16(uint32_t dst_smem, const void* src) {
    asm volatile("cp.async.cg.shared.global [%0], [%1], 16;"
                 :: "r"(dst_smem), "l"(src));
}
#define CP_COMMIT() asm volatile("cp.async.commit_group;" ::: "memory")
#define CP_WAIT(N)  asm volatile("cp.async.wait_group %0;" :: "n"(N) : "memory")

// ---------------------------------------------------------------------------
// Kernel 1: tf32 mma.sync per-head QKV projection.
//   Math unchanged from R14; epilogue now packs results to fp16 (half2).
// ---------------------------------------------------------------------------
#define QK_LD   68
#define QK_SMEM ((128 * QK_LD + 192 * QK_LD) * 4)   // 87040 B (dynamic)

__global__ __launch_bounds__(256, 1)
void qkv_mma_kernel(const float* __restrict__ x,
                    const float* __restrict__ Wq,
                    const float* __restrict__ bq) {
    extern __shared__ uint32_t qsm[];
    uint32_t* Xs = qsm;                   // [128][68], [r][k]
    uint32_t* Ws = qsm + 128 * QK_LD;     // [192][68], [n][k]  (transposed W)

    const int h    = blockIdx.y;
    const int row0 = blockIdx.x * 128;    // over B*T
    const int tid  = threadIdx.x;
    const int wid  = tid >> 5;
    const int lane = tid & 31;
    const int lrow = lane >> 2;           // 0..7
    const int lcol = lane & 3;            // 0..3

    const int warp_m = (wid & 1) * 64;    // 0 or 64
    const int warp_n = (wid >> 1) * 48;   // 0,48,96,144

#pragma unroll
    for (int it = 0; it < 8; it++) {
        const int i = it * 256 + tid;     // 0..2047 float4s
        const int r = i >> 4, c = (i & 15) * 4;
        const float4 v = *(const float4*)&x[(size_t)(row0 + r) * EE + h * HD + c];
        *(uint4*)&Xs[r * QK_LD + c] =
            make_uint4(f2tf32(v.x), f2tf32(v.y), f2tf32(v.z), f2tf32(v.w));
    }

    const float* Wh = Wq + (size_t)h * 64 * 192;
#pragma unroll
    for (int it = 0; it < 12; it++) {
        const int i = it * 256 + tid;     // 0..3071 float4s
        const int d = i / 48, c = (i % 48) * 4;
        const float4 v = *(const float4*)&Wh[d * 192 + c];
        Ws[(c + 0) * QK_LD + d] = f2tf32(v.x);
        Ws[(c + 1) * QK_LD + d] = f2tf32(v.y);
        Ws[(c + 2) * QK_LD + d] = f2tf32(v.z);
        Ws[(c + 3) * QK_LD + d] = f2tf32(v.w);
    }
    __syncthreads();

    float c[4][6][4];
#pragma unroll
    for (int m = 0; m < 4; m++)
#pragma unroll
        for (int n = 0; n < 6; n++)
#pragma unroll
            for (int f = 0; f < 4; f++) c[m][n][f] = 0.f;

#pragma unroll
    for (int ks = 0; ks < 8; ks++) {
        const int kk = ks * 8;
        uint32_t a[4][4], b[6][2];
#pragma unroll
        for (int m = 0; m < 4; m++) {
            const int ar = warp_m + m * 16 + lrow;
            a[m][0] = Xs[ar * QK_LD + kk + lcol];
            a[m][1] = Xs[(ar + 8) * QK_LD + kk + lcol];
            a[m][2] = Xs[ar * QK_LD + kk + 4 + lcol];
            a[m][3] = Xs[(ar + 8) * QK_LD + kk + 4 + lcol];
        }
#pragma unroll
        for (int n = 0; n < 6; n++) {
            const int br = warp_n + n * 8 + lrow;
            b[n][0] = Ws[br * QK_LD + kk + lcol];
            b[n][1] = Ws[br * QK_LD + kk + 4 + lcol];
        }
#pragma unroll
        for (int m = 0; m < 4; m++)
#pragma unroll
            for (int n = 0; n < 6; n++)
                mma_tf32_16x8x8(c[m][n][0], c[m][n][1], c[m][n][2], c[m][n][3],
                                a[m][0], a[m][1], a[m][2], a[m][3],
                                b[n][0], b[n][1]);
    }

    const float scale = (float)(1.0 / (8.0 + 1e-5));
#pragma unroll
    for (int n = 0; n < 6; n++) {
        const int col = warp_n + n * 8 + 2 * lcol;   // 0..191
        const int sec = col >> 6;                    // 0=q,1=k,2=v
        const int d   = col & 63;
        const float b0 = bq[h * 192 + col];
        const float b1 = bq[h * 192 + col + 1];
        __half* dst = (sec == 0) ? g_Q : (sec == 1) ? g_K : g_V;
        const float mul = (sec == 0) ? scale : 1.0f;
#pragma unroll
        for (int m = 0; m < 4; m++) {
            const int r  = row0 + warp_m + m * 16 + lrow;
            const int b_ = r / TT;
            const int t  = r - b_ * TT;
            const size_t off = ((size_t)(b_ * HH + h) * TT + t) * HD + d;
            *(uint32_t*)&dst[off] =
                pack_h2((c[m][n][0] + b0) * mul, (c[m][n][1] + b1) * mul);
            const size_t off2 = off + (size_t)8 * HD;   // row r+8, same b_ (128 | TT)
            *(uint32_t*)&dst[off2] =
                pack_h2((c[m][n][2] + b0) * mul, (c[m][n][3] + b1) * mul);
        }
    }
}

// ---------------------------------------------------------------------------
// Kernel 2 (R15): fp16 mma.m16n8k16 causal flash attention.
//   R14 datapath verbatim; Q/K/V now fp16 in global, so staging is a raw
//   16-byte copy (no conversion) — ~4x fewer staging instructions, half the
//   global K/V traffic. Numerics bit-identical to R14.
// ---------------------------------------------------------------------------
#define AT_P    36                              // uint32 (fp16x2) row stride
#define AT_SMEM (3 * 64 * AT_P * 4)             // 27648 B

__global__ __launch_bounds__(128, 4)
void attn_mma_kernel() {
    extern __shared__ uint32_t asm_[];
    uint32_t* Qs = asm_;                  // [64][36] fp16x2: Q tile, later P
    uint32_t* Ks = Qs + 64 * AT_P;        // [64][36] fp16x2: K, [c][d-pairs]
    uint32_t* Vs = Ks + 64 * AT_P;        // [64][36] fp16x2: V, [k][d-pairs]

    const int bh = blockIdx.y;
    const int qt = gridDim.x - 1 - blockIdx.x;    // big tiles first
    const int q0 = qt * 64;
    const __half* Qp = g_Q + (size_t)bh * TT * HD;
    const __half* Kp = g_K + (size_t)bh * TT * HD;
    const __half* Vp = g_V + (size_t)bh * TT * HD;

    const int tid  = threadIdx.x;
    const int wid  = tid >> 5;
    const int lane = tid & 31;
    const int lrow = lane >> 2;    // 0..7
    const int lcol = lane & 3;     // 0..3
    const int wm   = wid * 16;     // warp's row base within tile

    const uint32_t smem_u32 = (uint32_t)__cvta_generic_to_shared(asm_);
    // per-lane ldmatrix row base inside Vs: row (lane&15), row stride 144 B
    const uint32_t v_row_addr = smem_u32 + (2 * 64 * AT_P) * 4
                              + (uint32_t)(lane & 15) * (AT_P * 4);

    // ---- stage Q tile: raw fp16 copy, 4 x 16B per thread ----
#pragma unroll
    for (int it = 0; it < 4; it++) {
        const int i = it * 128 + tid;     // 0..511 16B-chunks
        const int r = i >> 3, c = i & 7;  // row, 16B-chunk (8 halves)
        *(uint4*)&Qs[r * AT_P + c * 4] =
            *(const uint4*)(Qp + (size_t)(q0 + r) * HD + c * 8);
    }
    __syncthreads();

    uint32_t qf[4][4];   // 4 k-steps of 16
#pragma unroll
    for (int ks = 0; ks < 4; ks++) {
        const int base = (wm + lrow) * AT_P + ks * 8 + lcol;
        qf[ks][0] = Qs[base];
        qf[ks][1] = Qs[base + 8 * AT_P];
        qf[ks][2] = Qs[base + 4];
        qf[ks][3] = Qs[base + 8 * AT_P + 4];
    }
    __syncthreads();   // Qs becomes the P buffer from here on

    float o[8][4];
#pragma unroll
    for (int n = 0; n < 8; n++)
#pragma unroll
        for (int f = 0; f < 4; f++) o[n][f] = 0.f;
    float m0 = -1e30f, m1 = -1e30f, l0 = 0.f, l1 = 0.f;

    const int r0g = q0 + wm + lrow;     // global row of frag-half 0
    const int r1g = r0g + 8;

    for (int kt = 0; kt <= qt; kt++) {
        const int kbase = kt * 64;
        __syncthreads();               // prev PV done with Ks/Vs
        // ---- stage K and V tiles: raw fp16 copy, 4 x (16B + 16B) ----
#pragma unroll
        for (int it = 0; it < 4; it++) {
            const int i = it * 128 + tid;
            const int r = i >> 3, c = i & 7;
            const size_t g = (size_t)(kbase + r) * HD + c * 8;
            *(uint4*)&Ks[r * AT_P + c * 4] = *(const uint4*)(Kp + g);
            *(uint4*)&Vs[r * AT_P + c * 4] = *(const uint4*)(Vp + g);
        }
        __syncthreads();

        // ---- S = Q K^T (fp16, K=16 per mma) ----
        float s[8][4];
#pragma unroll
        for (int n = 0; n < 8; n++)
#pragma unroll
            for (int f = 0; f < 4; f++) s[n][f] = 0.f;

#pragma unroll
        for (int ks = 0; ks < 4; ks++) {
#pragma unroll
            for (int n = 0; n < 8; n++) {
                const int kr = (n * 8 + lrow) * AT_P + ks * 8 + lcol;
                const uint32_t b0 = Ks[kr];
                const uint32_t b1 = Ks[kr + 4];
                mma_f16_16x8x16(s[n][0], s[n][1], s[n][2], s[n][3],
                                qf[ks][0], qf[ks][1], qf[ks][2], qf[ks][3],
                                b0, b1);
            }
        }

        if (kt == qt) {   // causal mask on diagonal tile
#pragma unroll
            for (int n = 0; n < 8; n++) {
                const int cg = kbase + n * 8 + 2 * lcol;
                if (cg     > r0g) s[n][0] = -1e30f;
                if (cg + 1 > r0g) s[n][1] = -1e30f;
                if (cg     > r1g) s[n][2] = -1e30f;
                if (cg + 1 > r1g) s[n][3] = -1e30f;
            }
        }

        // ---- online softmax (registers + quad shuffle) ----
        float mx0 = m0, mx1 = m1;
#pragma unroll
        for (int n = 0; n < 8; n++) {
            mx0 = fmaxf(mx0, fmaxf(s[n][0], s[n][1]));
            mx1 = fmaxf(mx1, fmaxf(s[n][2], s[n][3]));
        }
        mx0 = fmaxf(mx0, __shfl_xor_sync(0xffffffffu, mx0, 1));
        mx0 = fmaxf(mx0, __shfl_xor_sync(0xffffffffu, mx0, 2));
        mx1 = fmaxf(mx1, __shfl_xor_sync(0xffffffffu, mx1, 1));
        mx1 = fmaxf(mx1, __shfl_xor_sync(0xffffffffu, mx1, 2));

        float sum0 = 0.f, sum1 = 0.f;
#pragma unroll
        for (int n = 0; n < 8; n++) {
            s[n][0] = __expf(s[n][0] - mx0);
            s[n][1] = __expf(s[n][1] - mx0);
            s[n][2] = __expf(s[n][2] - mx1);
            s[n][3] = __expf(s[n][3] - mx1);
            sum0 += s[n][0] + s[n][1];
            sum1 += s[n][2] + s[n][3];
        }
        sum0 += __shfl_xor_sync(0xffffffffu, sum0, 1);
        sum0 += __shfl_xor_sync(0xffffffffu, sum0, 2);
        sum1 += __shfl_xor_sync(0xffffffffu, sum1, 1);
        sum1 += __shfl_xor_sync(0xffffffffu, sum1, 2);

        const float cf0 = __expf(m0 - mx0);
        const float cf1 = __expf(m1 - mx1);
        l0 = l0 * cf0 + sum0;  m0 = mx0;
        l1 = l1 * cf1 + sum1;  m1 = mx1;
#pragma unroll
        for (int n = 0; n < 8; n++) {
            o[n][0] *= cf0; o[n][1] *= cf0;
            o[n][2] *= cf1; o[n][3] *= cf1;
        }

        // ---- P -> per-warp fp16x2 smem rows, then PV ----
#pragma unroll
        for (int n = 0; n < 8; n++) {
            const int pr = (wm + lrow) * AT_P + n * 4 + lcol;
            Qs[pr]            = pack_h2(s[n][0], s[n][1]);
            Qs[pr + 8 * AT_P] = pack_h2(s[n][2], s[n][3]);
        }
        __syncwarp();

#pragma unroll
        for (int ks = 0; ks < 4; ks++) {
            const int pb = (wm + lrow) * AT_P + ks * 8 + lcol;
            const uint32_t a0 = Qs[pb];
            const uint32_t a1 = Qs[pb + 8 * AT_P];
            const uint32_t a2 = Qs[pb + 4];
            const uint32_t a3 = Qs[pb + 8 * AT_P + 4];
            const uint32_t vk = v_row_addr + (uint32_t)(ks * 16 * AT_P * 4);
#pragma unroll
            for (int n = 0; n < 8; n++) {
                uint32_t b0, b1;
                ldmatrix_x2_trans(b0, b1, vk + (uint32_t)(n * 16));
                mma_f16_16x8x16(o[n][0], o[n][1], o[n][2], o[n][3],
                                a0, a1, a2, a3, b0, b1);
            }
        }
        __syncwarp();
    }

    // ---- normalize and store ----
    const float inv0 = 1.0f / l0;
    const float inv1 = 1.0f / l1;
    const int b_ = bh >> 4, h = bh & 15;
    const size_t rowbase0 = (size_t)(b_ * TT + r0g) * EE + h * HD;
    const size_t rowbase1 = (size_t)(b_ * TT + r1g) * EE + h * HD;
#pragma unroll
    for (int n = 0; n < 8; n++) {
        const int d = n * 8 + 2 * lcol;
        *(float2*)&g_AO[rowbase0 + d] = make_float2(o[n][0] * inv0, o[n][1] * inv0);
        *(float2*)&g_AO[rowbase1 + d] = make_float2(o[n][2] * inv1, o[n][3] * inv1);
    }
}

// ---------------------------------------------------------------------------
// Kernel 3: tf32 mma.sync output projection, cp.async double-buffered
// (unchanged from R11 — known correct, 16 warps/SM register-bound)
// ---------------------------------------------------------------------------
#define PJ_LDA 36   // 32 + 4 pad (float4-aligned, conflict-free fragments)
#define PJ_SMEM (4 * 128 * PJ_LDA * 4)   // 73728 B

__global__ __launch_bounds__(256)
void proj_mma_kernel(const float* __restrict__ Wp,
                     const float* __restrict__ bp,
                     float* __restrict__ out) {
    extern __shared__ uint32_t psm[];
    uint32_t* Ab[2] = { psm,                  psm + 2 * 128 * PJ_LDA };
    uint32_t* Bb[2] = { psm + 128 * PJ_LDA,   psm + 3 * 128 * PJ_LDA };

    const int tid  = threadIdx.x;
    const int wid  = tid >> 5;
    const int lane = tid & 31;
    const int row0 = blockIdx.x * 128;
    const int col0 = blockIdx.y * 128;

    const uint32_t smem_u32 = (uint32_t)__cvta_generic_to_shared(psm);
    const uint32_t aoff[2] = { smem_u32,                         smem_u32 + 2 * 128 * PJ_LDA * 4 };
    const uint32_t boff[2] = { smem_u32 + 128 * PJ_LDA * 4,      smem_u32 + 3 * 128 * PJ_LDA * 4 };

    const int warp_m = (wid & 1) * 64;   // 0 or 64
    const int warp_n = (wid >> 1) * 32;  // 0,32,64,96

    auto stage = [&](int kt, int buf) {
        const int k0 = kt * 32;
#pragma unroll
        for (int it = 0; it < 4; it++) {
            const int lin = it * 1024 + tid * 4;   // 0..4095
            const int r = lin >> 5, cc = lin & 31;
            cp_async16(aoff[buf] + (uint32_t)(r * PJ_LDA + cc) * 4,
                       &g_AO[(size_t)(row0 + r) * EE + k0 + cc]);
            cp_async16(boff[buf] + (uint32_t)(r * PJ_LDA + cc) * 4,
                       &Wp[(size_t)(col0 + r) * EE + k0 + cc]);
        }
        CP_COMMIT();
    };

    float c[4][4][4];   // [m16][n8][frag]
#pragma unroll
    for (int m = 0; m < 4; m++)
#pragma unroll
        for (int n = 0; n < 4; n++)
#pragma unroll
            for (int f = 0; f < 4; f++) c[m][n][f] = 0.f;

    const int lrow = lane >> 2;    // 0..7
    const int lcol = lane & 3;     // 0..3

    stage(0, 0);
    stage(1, 1);

    for (int kt = 0; kt < EE / 32; kt++) {
        if (kt < EE / 32 - 1) { CP_WAIT(1); } else { CP_WAIT(0); }
        __syncthreads();
        const int cur = kt & 1;
        const uint32_t* As = Ab[cur];
        const uint32_t* Bs = Bb[cur];

#pragma unroll
        for (int ks = 0; ks < 4; ks++) {
            const int kk = ks * 8;
            uint32_t a[4][4], b[4][2];
#pragma unroll
            for (int m = 0; m < 4; m++) {
                const int ar = warp_m + m * 16 + lrow;
                a[m][0] = f2tf32(__uint_as_float(As[ar * PJ_LDA + kk + lcol]));
                a[m][1] = f2tf32(__uint_as_float(As[(ar + 8) * PJ_LDA + kk + lcol]));
                a[m][2] = f2tf32(__uint_as_float(As[ar * PJ_LDA + kk + 4 + lcol]));
                a[m][3] = f2tf32(__uint_as_float(As[(ar + 8) * PJ_LDA + kk + 4 + lcol]));
            }
#pragma unroll
            for (int n = 0; n < 4; n++) {
                const int br = warp_n + n * 8 + lrow;
                b[n][0] = f2tf32(__uint_as_float(Bs[br * PJ_LDA + kk + lcol]));
                b[n][1] = f2tf32(__uint_as_float(Bs[br * PJ_LDA + kk + 4 + lcol]));
            }
#pragma unroll
            for (int m = 0; m < 4; m++)
#pragma unroll
                for (int n = 0; n < 4; n++)
                    mma_tf32_16x8x8(c[m][n][0], c[m][n][1], c[m][n][2], c[m][n][3],
                                    a[m][0], a[m][1], a[m][2], a[m][3],
                                    b[n][0], b[n][1]);
        }

        __syncthreads();   // all warps done reading buf[cur] before refill
        if (kt + 2 < EE / 32) stage(kt + 2, cur);
    }

#pragma unroll
    for (int m = 0; m < 4; m++) {
#pragma unroll
        for (int n = 0; n < 4; n++) {
            const int col = col0 + warp_n + n * 8 + 2 * lcol;
            const int r1  = row0 + warp_m + m * 16 + lrow;
            const float b0 = bp[col], b1 = bp[col + 1];
            float2 o0 = make_float2(c[m][n][0] + b0, c[m][n][1] + b1);
            float2 o1 = make_float2(c[m][n][2] + b0, c[m][n][3] + b1);
            *(float2*)&out[(size_t)r1 * EE + col]       = o0;
            *(float2*)&out[(size_t)(r1 + 8) * EE + col] = o1;
        }
    }
}

// ---------------------------------------------------------------------------
// Launch
// ---------------------------------------------------------------------------
extern "C" void kernel_launch(void* const* d_in, const int* in_sizes, int n_in,
                              void* d_out, int out_size) {
    const float* x  = (const float*)d_in[0];
    const float* Wq = (const float*)d_in[1];
    const float* bq = (const float*)d_in[2];
    const float* Wp = (const float*)d_in[3];
    const float* bp = (const float*)d_in[4];
    float* out = (float*)d_out;

    cudaFuncSetAttribute(qkv_mma_kernel,  cudaFuncAttributeMaxDynamicSharedMemorySize, QK_SMEM);
    cudaFuncSetAttribute(attn_mma_kernel, cudaFuncAttributeMaxDynamicSharedMemorySize, AT_SMEM);
    cudaFuncSetAttribute(proj_mma_kernel, cudaFuncAttributeMaxDynamicSharedMemorySize, PJ_SMEM);

    qkv_mma_kernel<<<dim3(BT / 128, HH), 256, QK_SMEM>>>(x, Wq, bq);
    attn_mma_kernel<<<dim3(TT / 64, BB * HH), 128, AT_SMEM>>>();
    proj_mma_kernel<<<dim3(BT / 128, EE / 128), 256, PJ_SMEM>>>(Wp, bp, out);
}

// round 16
// speedup vs baseline: 1.9390x; 1.2737x over previous
#include <cuda_runtime.h>
#include <cuda_fp16.h>
#include <cstdint>

// Problem constants
#define BB 4
#define TT 2048
#define EE 1024
#define HH 16
#define HD 64
#define BT (BB * TT)   // 8192 rows

// ---------------------------------------------------------------------------
// Scratch (static __device__ arrays; no runtime allocation allowed)
// ---------------------------------------------------------------------------
__device__ __half g_Q[BB * HH * TT * HD];   // [b,h,t,d], q pre-scaled
__device__ __half g_K[BB * HH * TT * HD];
__device__ __half g_V[BB * HH * TT * HD];
__device__ __half g_AO[BT * EE];            // attention output, fp16
__device__ __half g_Wph[EE * EE];           // W_proj converted to fp16

// ---------------------------------------------------------------------------
// tf32 / fp16 / cp.async helpers (all sm_80+ PTX — valid at plain sm_100)
// ---------------------------------------------------------------------------
__device__ __forceinline__ uint32_t f2tf32(float f) {
    uint32_t r;
    asm("cvt.rna.tf32.f32 %0, %1;" : "=r"(r) : "f"(f));
    return r;
}

__device__ __forceinline__ uint32_t pack_h2(float lo, float hi) {
    __half2 h = __floats2half2_rn(lo, hi);
    return *reinterpret_cast<uint32_t*>(&h);
}

__device__ __forceinline__ void mma_tf32_16x8x8(
    float& c0, float& c1, float& c2, float& c3,
    uint32_t a0, uint32_t a1, uint32_t a2, uint32_t a3,
    uint32_t b0, uint32_t b1) {
    asm volatile(
        "mma.sync.aligned.m16n8k8.row.col.f32.tf32.tf32.f32 "
        "{%0,%1,%2,%3}, {%4,%5,%6,%7}, {%8,%9}, {%0,%1,%2,%3};"
        : "+f"(c0), "+f"(c1), "+f"(c2), "+f"(c3)
        : "r"(a0), "r"(a1), "r"(a2), "r"(a3), "r"(b0), "r"(b1));
}

// fp16 inputs, fp32 accumulate, K=16
__device__ __forceinline__ void mma_f16_16x8x16(
    float& c0, float& c1, float& c2, float& c3,
    uint32_t a0, uint32_t a1, uint32_t a2, uint32_t a3,
    uint32_t b0, uint32_t b1) {
    asm volatile(
        "mma.sync.aligned.m16n8k16.row.col.f32.f16.f16.f32 "
        "{%0,%1,%2,%3}, {%4,%5,%6,%7}, {%8,%9}, {%0,%1,%2,%3};"
        : "+f"(c0), "+f"(c1), "+f"(c2), "+f"(c3)
        : "r"(a0), "r"(a1), "r"(a2), "r"(a3), "r"(b0), "r"(b1));
}

__device__ __forceinline__ void ldmatrix_x2_trans(uint32_t& r0, uint32_t& r1,
                                                  uint32_t smem_addr) {
    asm volatile("ldmatrix.sync.aligned.m8n8.x2.trans.shared.b16 {%0,%1}, [%2];"
                 : "=r"(r0), "=r"(r1) : "r"(smem_addr));
}

__device__ __forceinline__ void cp_async16(uint32_t dst_smem, const void* src) {
    asm volatile("cp.async.cg.shared.global [%0], [%1], 16;"
                 :: "r"(dst_smem), "l"(src));
}
#define CP_COMMIT() asm volatile("cp.async.commit_group;" ::: "memory")
#define CP_WAIT(N)  asm volatile("cp.async.wait_group %0;" :: "n"(N) : "memory")

// ---------------------------------------------------------------------------
// Kernel 0: one-time Wp -> fp16 conversion (4 MB read, 2 MB write)
// ---------------------------------------------------------------------------
__global__ __launch_bounds__(256)
void wp_cvt_kernel(const float* __restrict__ Wp) {
    const int i = (blockIdx.x * 256 + threadIdx.x) * 8;   // 8 floats per thread
    const float4 v0 = *(const float4*)(Wp + i);
    const float4 v1 = *(const float4*)(Wp + i + 4);
    uint4 o;
    o.x = pack_h2(v0.x, v0.y);
    o.y = pack_h2(v0.z, v0.w);
    o.z = pack_h2(v1.x, v1.y);
    o.w = pack_h2(v1.z, v1.w);
    *(uint4*)&g_Wph[i] = o;
}

// ---------------------------------------------------------------------------
// Kernel 1: tf32 mma.sync per-head QKV projection (unchanged from R15)
// ---------------------------------------------------------------------------
#define QK_LD   68
#define QK_SMEM ((128 * QK_LD + 192 * QK_LD) * 4)   // 87040 B (dynamic)

__global__ __launch_bounds__(256, 1)
void qkv_mma_kernel(const float* __restrict__ x,
                    const float* __restrict__ Wq,
                    const float* __restrict__ bq) {
    extern __shared__ uint32_t qsm[];
    uint32_t* Xs = qsm;                   // [128][68], [r][k]
    uint32_t* Ws = qsm + 128 * QK_LD;     // [192][68], [n][k]  (transposed W)

    const int h    = blockIdx.y;
    const int row0 = blockIdx.x * 128;    // over B*T
    const int tid  = threadIdx.x;
    const int wid  = tid >> 5;
    const int lane = tid & 31;
    const int lrow = lane >> 2;           // 0..7
    const int lcol = lane & 3;            // 0..3

    const int warp_m = (wid & 1) * 64;    // 0 or 64
    const int warp_n = (wid >> 1) * 48;   // 0,48,96,144

#pragma unroll
    for (int it = 0; it < 8; it++) {
        const int i = it * 256 + tid;     // 0..2047 float4s
        const int r = i >> 4, c = (i & 15) * 4;
        const float4 v = *(const float4*)&x[(size_t)(row0 + r) * EE + h * HD + c];
        *(uint4*)&Xs[r * QK_LD + c] =
            make_uint4(f2tf32(v.x), f2tf32(v.y), f2tf32(v.z), f2tf32(v.w));
    }

    const float* Wh = Wq + (size_t)h * 64 * 192;
#pragma unroll
    for (int it = 0; it < 12; it++) {
        const int i = it * 256 + tid;     // 0..3071 float4s
        const int d = i / 48, c = (i % 48) * 4;
        const float4 v = *(const float4*)&Wh[d * 192 + c];
        Ws[(c + 0) * QK_LD + d] = f2tf32(v.x);
        Ws[(c + 1) * QK_LD + d] = f2tf32(v.y);
        Ws[(c + 2) * QK_LD + d] = f2tf32(v.z);
        Ws[(c + 3) * QK_LD + d] = f2tf32(v.w);
    }
    __syncthreads();

    float c[4][6][4];
#pragma unroll
    for (int m = 0; m < 4; m++)
#pragma unroll
        for (int n = 0; n < 6; n++)
#pragma unroll
            for (int f = 0; f < 4; f++) c[m][n][f] = 0.f;

#pragma unroll
    for (int ks = 0; ks < 8; ks++) {
        const int kk = ks * 8;
        uint32_t a[4][4], b[6][2];
#pragma unroll
        for (int m = 0; m < 4; m++) {
            const int ar = warp_m + m * 16 + lrow;
            a[m][0] = Xs[ar * QK_LD + kk + lcol];
            a[m][1] = Xs[(ar + 8) * QK_LD + kk + lcol];
            a[m][2] = Xs[ar * QK_LD + kk + 4 + lcol];
            a[m][3] = Xs[(ar + 8) * QK_LD + kk + 4 + lcol];
        }
#pragma unroll
        for (int n = 0; n < 6; n++) {
            const int br = warp_n + n * 8 + lrow;
            b[n][0] = Ws[br * QK_LD + kk + lcol];
            b[n][1] = Ws[br * QK_LD + kk + 4 + lcol];
        }
#pragma unroll
        for (int m = 0; m < 4; m++)
#pragma unroll
            for (int n = 0; n < 6; n++)
                mma_tf32_16x8x8(c[m][n][0], c[m][n][1], c[m][n][2], c[m][n][3],
                                a[m][0], a[m][1], a[m][2], a[m][3],
                                b[n][0], b[n][1]);
    }

    const float scale = (float)(1.0 / (8.0 + 1e-5));
#pragma unroll
    for (int n = 0; n < 6; n++) {
        const int col = warp_n + n * 8 + 2 * lcol;   // 0..191
        const int sec = col >> 6;                    // 0=q,1=k,2=v
        const int d   = col & 63;
        const float b0 = bq[h * 192 + col];
        const float b1 = bq[h * 192 + col + 1];
        __half* dst = (sec == 0) ? g_Q : (sec == 1) ? g_K : g_V;
        const float mul = (sec == 0) ? scale : 1.0f;
#pragma unroll
        for (int m = 0; m < 4; m++) {
            const int r  = row0 + warp_m + m * 16 + lrow;
            const int b_ = r / TT;
            const int t  = r - b_ * TT;
            const size_t off = ((size_t)(b_ * HH + h) * TT + t) * HD + d;
            *(uint32_t*)&dst[off] =
                pack_h2((c[m][n][0] + b0) * mul, (c[m][n][1] + b1) * mul);
            const size_t off2 = off + (size_t)8 * HD;   // row r+8, same b_ (128 | TT)
            *(uint32_t*)&dst[off2] =
                pack_h2((c[m][n][2] + b0) * mul, (c[m][n][3] + b1) * mul);
        }
    }
}

// ---------------------------------------------------------------------------
// Kernel 2: fp16 mma.m16n8k16 causal flash attention (R15 datapath; epilogue
// now writes g_AO as fp16 — the only change).
// ---------------------------------------------------------------------------
#define AT_P    36                              // uint32 (fp16x2) row stride
#define AT_SMEM (3 * 64 * AT_P * 4)             // 27648 B

__global__ __launch_bounds__(128, 4)
void attn_mma_kernel() {
    extern __shared__ uint32_t asm_[];
    uint32_t* Qs = asm_;                  // [64][36] fp16x2: Q tile, later P
    uint32_t* Ks = Qs + 64 * AT_P;        // [64][36] fp16x2: K, [c][d-pairs]
    uint32_t* Vs = Ks + 64 * AT_P;        // [64][36] fp16x2: V, [k][d-pairs]

    const int bh = blockIdx.y;
    const int qt = gridDim.x - 1 - blockIdx.x;    // big tiles first
    const int q0 = qt * 64;
    const __half* Qp = g_Q + (size_t)bh * TT * HD;
    const __half* Kp = g_K + (size_t)bh * TT * HD;
    const __half* Vp = g_V + (size_t)bh * TT * HD;

    const int tid  = threadIdx.x;
    const int wid  = tid >> 5;
    const int lane = tid & 31;
    const int lrow = lane >> 2;    // 0..7
    const int lcol = lane & 3;     // 0..3
    const int wm   = wid * 16;     // warp's row base within tile

    const uint32_t smem_u32 = (uint32_t)__cvta_generic_to_shared(asm_);
    // per-lane ldmatrix row base inside Vs: row (lane&15), row stride 144 B
    const uint32_t v_row_addr = smem_u32 + (2 * 64 * AT_P) * 4
                              + (uint32_t)(lane & 15) * (AT_P * 4);

    // ---- stage Q tile: raw fp16 copy, 4 x 16B per thread ----
#pragma unroll
    for (int it = 0; it < 4; it++) {
        const int i = it * 128 + tid;     // 0..511 16B-chunks
        const int r = i >> 3, c = i & 7;  // row, 16B-chunk (8 halves)
        *(uint4*)&Qs[r * AT_P + c * 4] =
            *(const uint4*)(Qp + (size_t)(q0 + r) * HD + c * 8);
    }
    __syncthreads();

    uint32_t qf[4][4];   // 4 k-steps of 16
#pragma unroll
    for (int ks = 0; ks < 4; ks++) {
        const int base = (wm + lrow) * AT_P + ks * 8 + lcol;
        qf[ks][0] = Qs[base];
        qf[ks][1] = Qs[base + 8 * AT_P];
        qf[ks][2] = Qs[base + 4];
        qf[ks][3] = Qs[base + 8 * AT_P + 4];
    }
    __syncthreads();   // Qs becomes the P buffer from here on

    float o[8][4];
#pragma unroll
    for (int n = 0; n < 8; n++)
#pragma unroll
        for (int f = 0; f < 4; f++) o[n][f] = 0.f;
    float m0 = -1e30f, m1 = -1e30f, l0 = 0.f, l1 = 0.f;

    const int r0g = q0 + wm + lrow;     // global row of frag-half 0
    const int r1g = r0g + 8;

    for (int kt = 0; kt <= qt; kt++) {
        const int kbase = kt * 64;
        __syncthreads();               // prev PV done with Ks/Vs
        // ---- stage K and V tiles: raw fp16 copy ----
#pragma unroll
        for (int it = 0; it < 4; it++) {
            const int i = it * 128 + tid;
            const int r = i >> 3, c = i & 7;
            const size_t g = (size_t)(kbase + r) * HD + c * 8;
            *(uint4*)&Ks[r * AT_P + c * 4] = *(const uint4*)(Kp + g);
            *(uint4*)&Vs[r * AT_P + c * 4] = *(const uint4*)(Vp + g);
        }
        __syncthreads();

        // ---- S = Q K^T (fp16, K=16 per mma) ----
        float s[8][4];
#pragma unroll
        for (int n = 0; n < 8; n++)
#pragma unroll
            for (int f = 0; f < 4; f++) s[n][f] = 0.f;

#pragma unroll
        for (int ks = 0; ks < 4; ks++) {
#pragma unroll
            for (int n = 0; n < 8; n++) {
                const int kr = (n * 8 + lrow) * AT_P + ks * 8 + lcol;
                const uint32_t b0 = Ks[kr];
                const uint32_t b1 = Ks[kr + 4];
                mma_f16_16x8x16(s[n][0], s[n][1], s[n][2], s[n][3],
                                qf[ks][0], qf[ks][1], qf[ks][2], qf[ks][3],
                                b0, b1);
            }
        }

        if (kt == qt) {   // causal mask on diagonal tile
#pragma unroll
            for (int n = 0; n < 8; n++) {
                const int cg = kbase + n * 8 + 2 * lcol;
                if (cg     > r0g) s[n][0] = -1e30f;
                if (cg + 1 > r0g) s[n][1] = -1e30f;
                if (cg     > r1g) s[n][2] = -1e30f;
                if (cg + 1 > r1g) s[n][3] = -1e30f;
            }
        }

        // ---- online softmax (registers + quad shuffle) ----
        float mx0 = m0, mx1 = m1;
#pragma unroll
        for (int n = 0; n < 8; n++) {
            mx0 = fmaxf(mx0, fmaxf(s[n][0], s[n][1]));
            mx1 = fmaxf(mx1, fmaxf(s[n][2], s[n][3]));
        }
        mx0 = fmaxf(mx0, __shfl_xor_sync(0xffffffffu, mx0, 1));
        mx0 = fmaxf(mx0, __shfl_xor_sync(0xffffffffu, mx0, 2));
        mx1 = fmaxf(mx1, __shfl_xor_sync(0xffffffffu, mx1, 1));
        mx1 = fmaxf(mx1, __shfl_xor_sync(0xffffffffu, mx1, 2));

        float sum0 = 0.f, sum1 = 0.f;
#pragma unroll
        for (int n = 0; n < 8; n++) {
            s[n][0] = __expf(s[n][0] - mx0);
            s[n][1] = __expf(s[n][1] - mx0);
            s[n][2] = __expf(s[n][2] - mx1);
            s[n][3] = __expf(s[n][3] - mx1);
            sum0 += s[n][0] + s[n][1];
            sum1 += s[n][2] + s[n][3];
        }
        sum0 += __shfl_xor_sync(0xffffffffu, sum0, 1);
        sum0 += __shfl_xor_sync(0xffffffffu, sum0, 2);
        sum1 += __shfl_xor_sync(0xffffffffu, sum1, 1);
        sum1 += __shfl_xor_sync(0xffffffffu, sum1, 2);

        const float cf0 = __expf(m0 - mx0);
        const float cf1 = __expf(m1 - mx1);
        l0 = l0 * cf0 + sum0;  m0 = mx0;
        l1 = l1 * cf1 + sum1;  m1 = mx1;
#pragma unroll
        for (int n = 0; n < 8; n++) {
            o[n][0] *= cf0; o[n][1] *= cf0;
            o[n][2] *= cf1; o[n][3] *= cf1;
        }

        // ---- P -> per-warp fp16x2 smem rows, then PV ----
#pragma unroll
        for (int n = 0; n < 8; n++) {
            const int pr = (wm + lrow) * AT_P + n * 4 + lcol;
            Qs[pr]            = pack_h2(s[n][0], s[n][1]);
            Qs[pr + 8 * AT_P] = pack_h2(s[n][2], s[n][3]);
        }
        __syncwarp();

#pragma unroll
        for (int ks = 0; ks < 4; ks++) {
            const int pb = (wm + lrow) * AT_P + ks * 8 + lcol;
            const uint32_t a0 = Qs[pb];
            const uint32_t a1 = Qs[pb + 8 * AT_P];
            const uint32_t a2 = Qs[pb + 4];
            const uint32_t a3 = Qs[pb + 8 * AT_P + 4];
            const uint32_t vk = v_row_addr + (uint32_t)(ks * 16 * AT_P * 4);
#pragma unroll
            for (int n = 0; n < 8; n++) {
                uint32_t b0, b1;
                ldmatrix_x2_trans(b0, b1, vk + (uint32_t)(n * 16));
                mma_f16_16x8x16(o[n][0], o[n][1], o[n][2], o[n][3],
                                a0, a1, a2, a3, b0, b1);
            }
        }
        __syncwarp();
    }

    // ---- normalize and store (fp16 output) ----
    const float inv0 = 1.0f / l0;
    const float inv1 = 1.0f / l1;
    const int b_ = bh >> 4, h = bh & 15;
    const size_t rowbase0 = (size_t)(b_ * TT + r0g) * EE + h * HD;
    const size_t rowbase1 = (size_t)(b_ * TT + r1g) * EE + h * HD;
#pragma unroll
    for (int n = 0; n < 8; n++) {
        const int d = n * 8 + 2 * lcol;
        *(uint32_t*)&g_AO[rowbase0 + d] = pack_h2(o[n][0] * inv0, o[n][1] * inv0);
        *(uint32_t*)&g_AO[rowbase1 + d] = pack_h2(o[n][2] * inv1, o[n][3] * inv1);
    }
}

// ---------------------------------------------------------------------------
// Kernel 3 (R16): fp16 mma.m16n8k16 output projection, cp.async double-buffered.
//   out[8192,1024] = g_AO(h) @ g_Wph^T + bp ; fp32 accumulate.
//   Tile 128x128, BK=64 halves; smem stride 36 uint32 (bank-validated).
// ---------------------------------------------------------------------------
#define PJ_P    36                                // uint32 (fp16x2) row stride
#define PJ_SMEM (4 * 128 * PJ_P * 4)              // 73728 B

__global__ __launch_bounds__(256)
void proj_f16_kernel(const float* __restrict__ bp,
                     float* __restrict__ out) {
    extern __shared__ uint32_t psm[];
    uint32_t* Ab[2] = { psm,                psm + 2 * 128 * PJ_P };
    uint32_t* Bb[2] = { psm + 128 * PJ_P,   psm + 3 * 128 * PJ_P };

    const int tid  = threadIdx.x;
    const int wid  = tid >> 5;
    const int lane = tid & 31;
    const int row0 = blockIdx.x * 128;
    const int col0 = blockIdx.y * 128;

    const uint32_t smem_u32 = (uint32_t)__cvta_generic_to_shared(psm);
    const uint32_t aoff[2] = { smem_u32,                      smem_u32 + 2 * 128 * PJ_P * 4 };
    const uint32_t boff[2] = { smem_u32 + 128 * PJ_P * 4,     smem_u32 + 3 * 128 * PJ_P * 4 };

    const int warp_m = (wid & 1) * 64;   // 0 or 64
    const int warp_n = (wid >> 1) * 32;  // 0,32,64,96

    // stage tile kt (BK=64 halves) into buffer buf: raw fp16 cp.async
    auto stage = [&](int kt, int buf) {
        const int k0 = kt * 64;
#pragma unroll
        for (int it = 0; it < 4; it++) {
            const int i = it * 256 + tid;      // 0..1023 16B-chunks
            const int r = i >> 3, c = i & 7;   // row, chunk (8 halves)
            cp_async16(aoff[buf] + (uint32_t)(r * PJ_P + c * 4) * 4,
                       &g_AO[(size_t)(row0 + r) * EE + k0 + c * 8]);
            cp_async16(boff[buf] + (uint32_t)(r * PJ_P + c * 4) * 4,
                       &g_Wph[(size_t)(col0 + r) * EE + k0 + c * 8]);
        }
        CP_COMMIT();
    };

    float c[4][4][4];   // [m16][n8][frag]
#pragma unroll
    for (int m = 0; m < 4; m++)
#pragma unroll
        for (int n = 0; n < 4; n++)
#pragma unroll
            for (int f = 0; f < 4; f++) c[m][n][f] = 0.f;

    const int lrow = lane >> 2;    // 0..7
    const int lcol = lane & 3;     // 0..3

    stage(0, 0);
    stage(1, 1);

    for (int kt = 0; kt < EE / 64; kt++) {   // 16 iterations
        if (kt < EE / 64 - 1) { CP_WAIT(1); } else { CP_WAIT(0); }
        __syncthreads();
        const int cur = kt & 1;
        const uint32_t* As = Ab[cur];
        const uint32_t* Bs = Bb[cur];

#pragma unroll
        for (int ks = 0; ks < 4; ks++) {     // 4 k-steps of 16
            const int kk = ks * 8;
            uint32_t a[4][4], b[4][2];
#pragma unroll
            for (int m = 0; m < 4; m++) {
                const int ar = warp_m + m * 16 + lrow;
                a[m][0] = As[ar * PJ_P + kk + lcol];
                a[m][1] = As[(ar + 8) * PJ_P + kk + lcol];
                a[m][2] = As[ar * PJ_P + kk + 4 + lcol];
                a[m][3] = As[(ar + 8) * PJ_P + kk + 4 + lcol];
            }
#pragma unroll
            for (int n = 0; n < 4; n++) {
                const int br = warp_n + n * 8 + lrow;
                b[n][0] = Bs[br * PJ_P + kk + lcol];
                b[n][1] = Bs[br * PJ_P + kk + 4 + lcol];
            }
#pragma unroll
            for (int m = 0; m < 4; m++)
#pragma unroll
                for (int n = 0; n < 4; n++)
                    mma_f16_16x8x16(c[m][n][0], c[m][n][1], c[m][n][2], c[m][n][3],
                                    a[m][0], a[m][1], a[m][2], a[m][3],
                                    b[n][0], b[n][1]);
        }

        __syncthreads();   // all warps done reading buf[cur] before refill
        if (kt + 2 < EE / 64) stage(kt + 2, cur);
    }

    // epilogue: fp32 bias add, fp32 store
#pragma unroll
    for (int m = 0; m < 4; m++) {
#pragma unroll
        for (int n = 0; n < 4; n++) {
            const int col = col0 + warp_n + n * 8 + 2 * lcol;
            const int r1  = row0 + warp_m + m * 16 + lrow;
            const float b0 = bp[col], b1 = bp[col + 1];
            float2 o0 = make_float2(c[m][n][0] + b0, c[m][n][1] + b1);
            float2 o1 = make_float2(c[m][n][2] + b0, c[m][n][3] + b1);
            *(float2*)&out[(size_t)r1 * EE + col]       = o0;
            *(float2*)&out[(size_t)(r1 + 8) * EE + col] = o1;
        }
    }
}

// ---------------------------------------------------------------------------
// Launch
// ---------------------------------------------------------------------------
extern "C" void kernel_launch(void* const* d_in, const int* in_sizes, int n_in,
                              void* d_out, int out_size) {
    const float* x  = (const float*)d_in[0];
    const float* Wq = (const float*)d_in[1];
    const float* bq = (const float*)d_in[2];
    const float* Wp = (const float*)d_in[3];
    const float* bp = (const float*)d_in[4];
    float* out = (float*)d_out;

    cudaFuncSetAttribute(qkv_mma_kernel,  cudaFuncAttributeMaxDynamicSharedMemorySize, QK_SMEM);
    cudaFuncSetAttribute(attn_mma_kernel, cudaFuncAttributeMaxDynamicSharedMemorySize, AT_SMEM);
    cudaFuncSetAttribute(proj_f16_kernel, cudaFuncAttributeMaxDynamicSharedMemorySize, PJ_SMEM);

    wp_cvt_kernel<<<EE * EE / (256 * 8), 256>>>(Wp);
    qkv_mma_kernel<<<dim3(BT / 128, HH), 256, QK_SMEM>>>(x, Wq, bq);
    attn_mma_kernel<<<dim3(TT / 64, BB * HH), 128, AT_SMEM>>>();
    proj_f16_kernel<<<dim3(BT / 128, EE / 128), 256, PJ_SMEM>>>(bp, out);
}